// round 6
// baseline (speedup 1.0000x reference)
#include <cuda_runtime.h>
#include <math.h>

#define NB   2
#define NV   400
#define NH   128
#define NBV  800          // B*V
#define NBVV 320000       // B*V*V
#define JT   80           // row tile
#define KC   32           // K chunk
#define BN_EPS 1e-5f

// ---- scratch (device globals; no allocation allowed) ----
__device__ __align__(16) float g_lin[4 * NBV * NH];   // [0]=Ux [1]=Vx [2]=Ax [3]=Bx
__device__ __align__(16) float g_agg[NBV * NH];       // sum_j Vx*gate
__device__ float g_sum_e[NH];
__device__ float g_sq_e[NH];

struct LinParams {
    const float *W0, *W1, *W2, *W3;
    const float *b0, *b1, *b2, *b3;
};

// ---------------------------------------------------------------------------
// zero accumulators
// ---------------------------------------------------------------------------
__global__ void zero_kernel() {
    int i = blockIdx.x * blockDim.x + threadIdx.x;
    if (i < NBV * NH) g_agg[i] = 0.f;
    if (i < NH) { g_sum_e[i] = 0.f; g_sq_e[i] = 0.f; }
}

// ---------------------------------------------------------------------------
// four small linears: y = x @ W^T + b   (M=800, K=N=128, z selects matrix)
// ---------------------------------------------------------------------------
__global__ void __launch_bounds__(256) lin4_kernel(const float* __restrict__ x, LinParams p)
{
    __shared__ float As[JT][KC + 1];
    __shared__ float Bs[KC][NH + 4];
    int tid = threadIdx.x;
    int tx = tid & 15, ty = tid >> 4;
    int z = blockIdx.y;
    const float* W; const float* bias;
    if (z == 0)      { W = p.W0; bias = p.b0; }
    else if (z == 1) { W = p.W1; bias = p.b1; }
    else if (z == 2) { W = p.W2; bias = p.b2; }
    else             { W = p.W3; bias = p.b3; }
    int r0 = blockIdx.x * JT;
    const float* Arow = x + r0 * NH;

    float acc[5][8];
    #pragma unroll
    for (int s = 0; s < 5; ++s)
        #pragma unroll
        for (int c = 0; c < 8; ++c) acc[s][c] = 0.f;

    for (int kc = 0; kc < NH; kc += KC) {
        #pragma unroll
        for (int it = 0; it < 10; ++it) {
            int idx = tid + it * 256;
            int r = idx >> 5, k = idx & 31;
            As[r][k] = Arow[r * NH + kc + k];
        }
        #pragma unroll
        for (int it = 0; it < 16; ++it) {
            int idx = tid + it * 256;
            int n = idx >> 5, k = idx & 31;
            Bs[k][n] = W[n * NH + kc + k];
        }
        __syncthreads();
        #pragma unroll
        for (int k = 0; k < KC; ++k) {
            float a[5];
            #pragma unroll
            for (int s = 0; s < 5; ++s) a[s] = As[ty + 16 * s][k];
            float4 u = *(const float4*)&Bs[k][4 * tx];
            float4 w = *(const float4*)&Bs[k][64 + 4 * tx];
            #pragma unroll
            for (int s = 0; s < 5; ++s) {
                acc[s][0] += a[s] * u.x; acc[s][1] += a[s] * u.y;
                acc[s][2] += a[s] * u.z; acc[s][3] += a[s] * u.w;
                acc[s][4] += a[s] * w.x; acc[s][5] += a[s] * w.y;
                acc[s][6] += a[s] * w.z; acc[s][7] += a[s] * w.w;
            }
        }
        __syncthreads();
    }

    int n0 = 4 * tx, n1 = 64 + 4 * tx;
    float cb[8];
    *(float4*)&cb[0] = *(const float4*)&bias[n0];
    *(float4*)&cb[4] = *(const float4*)&bias[n1];
    float* out = g_lin + z * NBV * NH;
    #pragma unroll
    for (int s = 0; s < 5; ++s) {
        int r = r0 + ty + 16 * s;
        float ov[8];
        #pragma unroll
        for (int c = 0; c < 8; ++c) ov[c] = acc[s][c] + cb[c];
        *(float4*)&out[r * NH + n0] = *(float4*)&ov[0];
        *(float4*)&out[r * NH + n1] = *(float4*)&ov[4];
    }
}

// ---------------------------------------------------------------------------
// big fused kernel: Ce GEMM + e_new + channel sums + sigmoid gates + agg
// writes raw e_new into eout (normalized in place later)
// grid: (V/JT = 5, B*V = 800), block 256
// ---------------------------------------------------------------------------
__global__ void __launch_bounds__(256) egemm_kernel(
    const float* __restrict__ e, const float* __restrict__ Cw,
    const float* __restrict__ Cb, float* __restrict__ enew)
{
    __shared__ float As[JT][KC + 1];
    __shared__ float Bs[KC][NH + 4];
    __shared__ float sh_sum[NH], sh_sq[NH], sh_agg[NH];
    int tid = threadIdx.x;
    int tx = tid & 15, ty = tid >> 4;
    int bi = blockIdx.y;          // b*V + i
    int b  = bi / NV;
    int j0 = blockIdx.x * JT;
    if (tid < NH) { sh_sum[tid] = 0.f; sh_sq[tid] = 0.f; sh_agg[tid] = 0.f; }

    const float* Arow = e + ((size_t)bi * NV + j0) * NH;

    float acc[5][8];
    #pragma unroll
    for (int s = 0; s < 5; ++s)
        #pragma unroll
        for (int c = 0; c < 8; ++c) acc[s][c] = 0.f;

    for (int kc = 0; kc < NH; kc += KC) {
        #pragma unroll
        for (int it = 0; it < 10; ++it) {
            int idx = tid + it * 256;
            int r = idx >> 5, k = idx & 31;
            As[r][k] = Arow[r * NH + kc + k];
        }
        #pragma unroll
        for (int it = 0; it < 16; ++it) {
            int idx = tid + it * 256;
            int n = idx >> 5, k = idx & 31;
            Bs[k][n] = Cw[n * NH + kc + k];
        }
        __syncthreads();
        #pragma unroll
        for (int k = 0; k < KC; ++k) {
            float a[5];
            #pragma unroll
            for (int s = 0; s < 5; ++s) a[s] = As[ty + 16 * s][k];
            float4 u = *(const float4*)&Bs[k][4 * tx];
            float4 w = *(const float4*)&Bs[k][64 + 4 * tx];
            #pragma unroll
            for (int s = 0; s < 5; ++s) {
                acc[s][0] += a[s] * u.x; acc[s][1] += a[s] * u.y;
                acc[s][2] += a[s] * u.z; acc[s][3] += a[s] * u.w;
                acc[s][4] += a[s] * w.x; acc[s][5] += a[s] * w.y;
                acc[s][6] += a[s] * w.z; acc[s][7] += a[s] * w.w;
            }
        }
        __syncthreads();
    }

    // epilogue: e_new = Ce + Cb + Ax[b,j] + Bx[b,i]; gates; stats; agg
    const float* Vx = g_lin + 1 * NBV * NH;
    const float* Ax = g_lin + 2 * NBV * NH;
    const float* Bx = g_lin + 3 * NBV * NH;
    int n0 = 4 * tx, n1 = 64 + 4 * tx;
    float cb[8], bxv[8];
    *(float4*)&cb[0]  = *(const float4*)&Cb[n0];
    *(float4*)&cb[4]  = *(const float4*)&Cb[n1];
    *(float4*)&bxv[0] = *(const float4*)&Bx[bi * NH + n0];
    *(float4*)&bxv[4] = *(const float4*)&Bx[bi * NH + n1];

    float psum[8], psq[8], pagg[8];
    #pragma unroll
    for (int c = 0; c < 8; ++c) { psum[c] = 0.f; psq[c] = 0.f; pagg[c] = 0.f; }

    #pragma unroll
    for (int s = 0; s < 5; ++s) {
        int j = j0 + ty + 16 * s;
        int xrow = (b * NV + j) * NH;
        float ax[8], vx[8], ev[8];
        *(float4*)&ax[0] = *(const float4*)&Ax[xrow + n0];
        *(float4*)&ax[4] = *(const float4*)&Ax[xrow + n1];
        *(float4*)&vx[0] = *(const float4*)&Vx[xrow + n0];
        *(float4*)&vx[4] = *(const float4*)&Vx[xrow + n1];
        #pragma unroll
        for (int c = 0; c < 8; ++c) {
            float v = acc[s][c] + cb[c] + ax[c] + bxv[c];
            ev[c] = v;
            psum[c] += v;
            psq[c]  += v * v;
            float gate = 1.f / (1.f + expf(-v));
            pagg[c] += vx[c] * gate;
        }
        size_t erow = ((size_t)bi * NV + j) * NH;
        *(float4*)&enew[erow + n0] = *(float4*)&ev[0];
        *(float4*)&enew[erow + n1] = *(float4*)&ev[4];
    }

    // reduce ty pairs inside each warp (lanes tx and 16+tx)
    #pragma unroll
    for (int c = 0; c < 8; ++c) {
        psum[c] += __shfl_xor_sync(0xffffffffu, psum[c], 16);
        psq[c]  += __shfl_xor_sync(0xffffffffu, psq[c], 16);
        pagg[c] += __shfl_xor_sync(0xffffffffu, pagg[c], 16);
    }
    if ((ty & 1) == 0) {
        #pragma unroll
        for (int c = 0; c < 8; ++c) {
            int n = (c < 4) ? (n0 + c) : (n1 + c - 4);
            atomicAdd(&sh_sum[n], psum[c]);
            atomicAdd(&sh_sq[n],  psq[c]);
            atomicAdd(&sh_agg[n], pagg[c]);
        }
    }
    __syncthreads();
    if (tid < NH) {
        atomicAdd(&g_sum_e[tid], sh_sum[tid]);
        atomicAdd(&g_sq_e[tid],  sh_sq[tid]);
        atomicAdd(&g_agg[bi * NH + tid], sh_agg[tid]);
    }
}

// ---------------------------------------------------------------------------
// x path: x_new = Ux + agg; BN over 800 rows; ReLU. Single block.
// ---------------------------------------------------------------------------
__global__ void __launch_bounds__(1024) xout_kernel(
    const float* __restrict__ gx, const float* __restrict__ bx,
    float* __restrict__ xout)
{
    __shared__ float sh_s[8 * NH], sh_q[8 * NH];
    __shared__ float scale[NH], shift[NH];
    int tid = threadIdx.x;
    int h = tid & 127, g = tid >> 7;
    const float* Ux = g_lin;   // z=0
    float s = 0.f, q = 0.f;
    for (int r = g; r < NBV; r += 8) {
        float v = Ux[r * NH + h] + g_agg[r * NH + h];
        s += v; q += v * v;
    }
    sh_s[g * NH + h] = s; sh_q[g * NH + h] = q;
    __syncthreads();
    if (g == 0) {
        for (int gg = 1; gg < 8; ++gg) { s += sh_s[gg * NH + h]; q += sh_q[gg * NH + h]; }
        float m   = s * (1.f / NBV);
        float var = q * (1.f / NBV) - m * m;
        float sc  = gx[h] * rsqrtf(var + BN_EPS);
        scale[h] = sc; shift[h] = bx[h] - m * sc;
    }
    __syncthreads();
    for (int r = g; r < NBV; r += 8) {
        float v = Ux[r * NH + h] + g_agg[r * NH + h];
        float o = v * scale[h] + shift[h];
        xout[r * NH + h] = fmaxf(o, 0.f);
    }
}

// ---------------------------------------------------------------------------
// e path: BN(e_new) + ReLU, in place over eout, float4
// ---------------------------------------------------------------------------
__global__ void __launch_bounds__(256) eout_kernel(
    const float* __restrict__ ge, const float* __restrict__ be,
    float* __restrict__ eout)
{
    __shared__ float scale[NH], shift[NH];
    int tid = threadIdx.x;
    if (tid < NH) {
        float m   = g_sum_e[tid] * (1.f / NBVV);
        float var = g_sq_e[tid]  * (1.f / NBVV) - m * m;
        float sc  = __ldg(&ge[tid]) * rsqrtf(var + BN_EPS);
        scale[tid] = sc; shift[tid] = __ldg(&be[tid]) - m * sc;
    }
    __syncthreads();
    float4* buf = (float4*)eout;
    int total = NBVV * NH / 4;                    // 10,240,000
    int stride = gridDim.x * blockDim.x;
    for (int i = blockIdx.x * blockDim.x + tid; i < total; i += stride) {
        float4 v = buf[i];
        int h = (i * 4) & 127;
        v.x = fmaxf(v.x * scale[h]     + shift[h],     0.f);
        v.y = fmaxf(v.y * scale[h + 1] + shift[h + 1], 0.f);
        v.z = fmaxf(v.z * scale[h + 2] + shift[h + 2], 0.f);
        v.w = fmaxf(v.w * scale[h + 3] + shift[h + 3], 0.f);
        buf[i] = v;
    }
}

// ---------------------------------------------------------------------------
extern "C" void kernel_launch(void* const* d_in, const int* in_sizes, int n_in,
                              void* d_out, int out_size)
{
    (void)in_sizes; (void)n_in; (void)out_size;
    const float* x  = (const float*)d_in[0];
    const float* e  = (const float*)d_in[1];
    // d_in[2] = graph (unused by reference)
    const float* Uw = (const float*)d_in[3];  const float* Ub = (const float*)d_in[4];
    const float* Vw = (const float*)d_in[5];  const float* Vb = (const float*)d_in[6];
    const float* Aw = (const float*)d_in[7];  const float* Ab = (const float*)d_in[8];
    const float* Bw = (const float*)d_in[9];  const float* Bb = (const float*)d_in[10];
    const float* Cw = (const float*)d_in[11]; const float* Cb = (const float*)d_in[12];
    const float* gx = (const float*)d_in[13]; const float* bx = (const float*)d_in[14];
    const float* ge = (const float*)d_in[15]; const float* be = (const float*)d_in[16];

    float* xout = (float*)d_out;               // (B,V,H)   = 102400 floats
    float* eout = xout + NBV * NH;             // (B,V,V,H) = 40,960,000 floats

    zero_kernel<<<(NBV * NH + 255) / 256, 256>>>();

    LinParams p;
    p.W0 = Uw; p.W1 = Vw; p.W2 = Aw; p.W3 = Bw;
    p.b0 = Ub; p.b1 = Vb; p.b2 = Ab; p.b3 = Bb;
    lin4_kernel<<<dim3(NBV / JT, 4), 256>>>(x, p);

    egemm_kernel<<<dim3(NV / JT, NBV), 256>>>(e, Cw, Cb, eout);

    xout_kernel<<<1, 1024>>>(gx, bx, xout);
    eout_kernel<<<3072, 256>>>(ge, be, eout);
}

// round 10
// speedup vs baseline: 1.0088x; 1.0088x over previous
#include <cuda_runtime.h>
#include <math.h>
#include <stdint.h>

#define NB   2
#define NV   400
#define NH   128
#define NBV  800          // B*V
#define NBVV 320000       // B*V*V
#define BJ   64           // j rows per block in egemm_mma
#define BN_EPS 1e-5f

#define SEW 132           // padded row stride (u32 words) for 128-wide tiles

// ---- scratch (device globals; no allocation allowed) ----
__device__ __align__(16) float g_lin[4 * NBV * NH];   // [0]=Ux [1]=Vx [2]=Ax [3]=Bx
__device__ __align__(16) float g_agg[NBV * NH];       // sum_j Vx*gate
__device__ float g_sum_e[NH];
__device__ float g_sq_e[NH];
__device__ float g_xsum[NH];
__device__ float g_xsq[NH];

struct LinParams {
    const float *W0, *W1, *W2, *W3;
    const float *b0, *b1, *b2, *b3;
};

__device__ __forceinline__ uint32_t f2tf32(float f) {
    uint32_t u;
    asm("cvt.rna.tf32.f32 %0, %1;" : "=r"(u) : "f"(f));
    return u;
}

#define MMA_TF32(d, a, b0v, b1v)                                             \
    asm volatile(                                                            \
        "mma.sync.aligned.m16n8k8.row.col.f32.tf32.tf32.f32 "                \
        "{%0,%1,%2,%3}, {%4,%5,%6,%7}, {%8,%9}, {%0,%1,%2,%3};"              \
        : "+f"((d)[0]), "+f"((d)[1]), "+f"((d)[2]), "+f"((d)[3])             \
        : "r"((a)[0]), "r"((a)[1]), "r"((a)[2]), "r"((a)[3]),                \
          "r"(b0v), "r"(b1v))

// ---------------------------------------------------------------------------
// zero accumulators
// ---------------------------------------------------------------------------
__global__ void zero_kernel() {
    int i = blockIdx.x * blockDim.x + threadIdx.x;
    if (i < NBV * NH) g_agg[i] = 0.f;
    if (i < NH) {
        g_sum_e[i] = 0.f; g_sq_e[i] = 0.f;
        g_xsum[i] = 0.f;  g_xsq[i] = 0.f;
    }
}

// ---------------------------------------------------------------------------
// four small linears: y = x @ W^T + b   (M=800, K=N=128, z selects matrix)
// ---------------------------------------------------------------------------
__global__ void __launch_bounds__(256) lin4_kernel(const float* __restrict__ x, LinParams p)
{
    __shared__ float As[80][33];
    __shared__ float Bs[32][NH + 4];
    int tid = threadIdx.x;
    int tx = tid & 15, ty = tid >> 4;
    int z = blockIdx.y;
    const float* W; const float* bias;
    if (z == 0)      { W = p.W0; bias = p.b0; }
    else if (z == 1) { W = p.W1; bias = p.b1; }
    else if (z == 2) { W = p.W2; bias = p.b2; }
    else             { W = p.W3; bias = p.b3; }
    int r0 = blockIdx.x * 80;
    const float* Arow = x + r0 * NH;

    float acc[5][8];
    #pragma unroll
    for (int s = 0; s < 5; ++s)
        #pragma unroll
        for (int c = 0; c < 8; ++c) acc[s][c] = 0.f;

    for (int kc = 0; kc < NH; kc += 32) {
        #pragma unroll
        for (int it = 0; it < 10; ++it) {
            int idx = tid + it * 256;
            int r = idx >> 5, k = idx & 31;
            As[r][k] = Arow[r * NH + kc + k];
        }
        #pragma unroll
        for (int it = 0; it < 16; ++it) {
            int idx = tid + it * 256;
            int n = idx >> 5, k = idx & 31;
            Bs[k][n] = W[n * NH + kc + k];
        }
        __syncthreads();
        #pragma unroll
        for (int k = 0; k < 32; ++k) {
            float a[5];
            #pragma unroll
            for (int s = 0; s < 5; ++s) a[s] = As[ty + 16 * s][k];
            float4 u = *(const float4*)&Bs[k][4 * tx];
            float4 w = *(const float4*)&Bs[k][64 + 4 * tx];
            #pragma unroll
            for (int s = 0; s < 5; ++s) {
                acc[s][0] += a[s] * u.x; acc[s][1] += a[s] * u.y;
                acc[s][2] += a[s] * u.z; acc[s][3] += a[s] * u.w;
                acc[s][4] += a[s] * w.x; acc[s][5] += a[s] * w.y;
                acc[s][6] += a[s] * w.z; acc[s][7] += a[s] * w.w;
            }
        }
        __syncthreads();
    }

    int n0 = 4 * tx, n1 = 64 + 4 * tx;
    float cb[8];
    *(float4*)&cb[0] = *(const float4*)&bias[n0];
    *(float4*)&cb[4] = *(const float4*)&bias[n1];
    float* out = g_lin + z * NBV * NH;
    #pragma unroll
    for (int s = 0; s < 5; ++s) {
        int r = r0 + ty + 16 * s;
        float ov[8];
        #pragma unroll
        for (int c = 0; c < 8; ++c) ov[c] = acc[s][c] + cb[c];
        *(float4*)&out[r * NH + n0] = *(float4*)&ov[0];
        *(float4*)&out[r * NH + n1] = *(float4*)&ov[4];
    }
}

// ---------------------------------------------------------------------------
// tf32 tensor-core fused kernel:
//   Ce = e @ Cw^T via mma.m16n8k8.tf32 ; e_new = Ce+Cb+Ax+Bx -> enew (raw)
//   + per-channel sum/sumsq (BN) + sigmoid-gated agg accumulation
// grid: (ceil(400/64)=7, B*V=800), block 256 (8 warps)
// warp w: mq=w>>2 (32-row half), nq=w&3 (32-col quarter)
// ---------------------------------------------------------------------------
__global__ void __launch_bounds__(256) egemm_mma_kernel(
    const float* __restrict__ e, const float* __restrict__ Cw,
    const float* __restrict__ Cb, float* __restrict__ enew)
{
    extern __shared__ uint32_t dyn[];
    uint32_t* sE = dyn;                    // [64][SEW] tf32
    uint32_t* sB = dyn + 64 * SEW;         // [128][SEW] tf32
    float* aux   = (float*)(dyn + 64 * SEW + 128 * SEW);
    float* sh_sum = aux;                   // [128]
    float* sh_sq  = aux + NH;              // [128]
    float* sh_agg = aux + 2 * NH;          // [128]
    float* cbS    = aux + 3 * NH;          // [128]
    float* bxS    = aux + 4 * NH;          // [128]
    // phase-2 reuse of tile space:
    float* sAx = (float*)dyn;              // [64][SEW]
    float* sVx = (float*)(dyn + 64 * SEW); // [64][SEW]

    int tid  = threadIdx.x;
    int lane = tid & 31;
    int wid  = tid >> 5;
    int gid  = lane >> 2, tig = lane & 3;
    int mq = wid >> 2;        // 0..1
    int nq = wid & 3;         // 0..3

    int bi = blockIdx.y;              // b*V + i
    int b  = bi / NV;
    int j0 = blockIdx.x * BJ;
    int rows = NV - j0; if (rows > BJ) rows = BJ;

    // ---- phase 1: stage E (tf32), Cw (tf32), bias/Bx rows ----
    const float* Erow = e + ((size_t)bi * NV + j0) * NH;
    #pragma unroll
    for (int it = 0; it < 8; ++it) {
        int idx = tid + it * 256;         // 64*32
        int r = idx >> 5, c4 = (idx & 31) * 4;
        float4 v = make_float4(0.f, 0.f, 0.f, 0.f);
        if (r < rows) v = *(const float4*)&Erow[r * NH + c4];
        uint32_t* d = &sE[r * SEW + c4];
        d[0] = f2tf32(v.x); d[1] = f2tf32(v.y); d[2] = f2tf32(v.z); d[3] = f2tf32(v.w);
    }
    #pragma unroll
    for (int it = 0; it < 16; ++it) {
        int idx = tid + it * 256;         // 128*32
        int r = idx >> 5, c4 = (idx & 31) * 4;
        float4 v = *(const float4*)&Cw[r * NH + c4];
        uint32_t* d = &sB[r * SEW + c4];
        d[0] = f2tf32(v.x); d[1] = f2tf32(v.y); d[2] = f2tf32(v.z); d[3] = f2tf32(v.w);
    }
    if (tid < NH) {
        cbS[tid] = Cb[tid];
        bxS[tid] = g_lin[3 * NBV * NH + bi * NH + tid];   // Bx row
        sh_sum[tid] = 0.f; sh_sq[tid] = 0.f; sh_agg[tid] = 0.f;
    }
    __syncthreads();

    // ---- phase 2: mma mainloop, K=128 in 16 steps of 8 ----
    float acc[2][4][4];
    #pragma unroll
    for (int mt = 0; mt < 2; ++mt)
        #pragma unroll
        for (int nt = 0; nt < 4; ++nt)
            #pragma unroll
            for (int c = 0; c < 4; ++c) acc[mt][nt][c] = 0.f;

    #pragma unroll
    for (int k0 = 0; k0 < NH; k0 += 8) {
        uint32_t a[2][4];
        #pragma unroll
        for (int mt = 0; mt < 2; ++mt) {
            int r = mq * 32 + mt * 16 + gid;
            a[mt][0] = sE[r * SEW + k0 + tig];
            a[mt][1] = sE[(r + 8) * SEW + k0 + tig];
            a[mt][2] = sE[r * SEW + k0 + tig + 4];
            a[mt][3] = sE[(r + 8) * SEW + k0 + tig + 4];
        }
        #pragma unroll
        for (int nt = 0; nt < 4; ++nt) {
            int n = nq * 32 + nt * 8 + gid;
            uint32_t b0 = sB[n * SEW + k0 + tig];
            uint32_t b1 = sB[n * SEW + k0 + tig + 4];
            MMA_TF32(acc[0][nt], a[0], b0, b1);
            MMA_TF32(acc[1][nt], a[1], b0, b1);
        }
    }
    __syncthreads();

    // ---- phase 3: stage Ax/Vx rows into reused smem ----
    const float* AxG = g_lin + 2 * NBV * NH;
    const float* VxG = g_lin + 1 * NBV * NH;
    #pragma unroll
    for (int it = 0; it < 8; ++it) {
        int idx = tid + it * 256;
        int r = idx >> 5, c4 = (idx & 31) * 4;
        float4 av = make_float4(0.f, 0.f, 0.f, 0.f);
        float4 vv = av;
        if (r < rows) {
            size_t base = ((size_t)(b * NV + j0 + r)) * NH + c4;
            av = *(const float4*)&AxG[base];
            vv = *(const float4*)&VxG[base];
        }
        *(float4*)&sAx[r * SEW + c4] = av;
        *(float4*)&sVx[r * SEW + c4] = vv;
    }
    __syncthreads();

    // ---- phase 4: epilogue ----
    float s[4][2], q[4][2], ag[4][2];
    #pragma unroll
    for (int nt = 0; nt < 4; ++nt)
        #pragma unroll
        for (int c = 0; c < 2; ++c) { s[nt][c] = 0.f; q[nt][c] = 0.f; ag[nt][c] = 0.f; }

    #pragma unroll
    for (int mt = 0; mt < 2; ++mt) {
        #pragma unroll
        for (int half = 0; half < 2; ++half) {
            int rr = mq * 32 + mt * 16 + half * 8 + gid;   // local row
            if (rr < rows) {
                size_t grow = ((size_t)bi * NV + j0 + rr) * NH;
                #pragma unroll
                for (int nt = 0; nt < 4; ++nt) {
                    int c0 = nq * 32 + nt * 8 + 2 * tig;
                    float ev0 = acc[mt][nt][half * 2]     + cbS[c0]     + sAx[rr * SEW + c0]     + bxS[c0];
                    float ev1 = acc[mt][nt][half * 2 + 1] + cbS[c0 + 1] + sAx[rr * SEW + c0 + 1] + bxS[c0 + 1];
                    float2 st; st.x = ev0; st.y = ev1;
                    *(float2*)&enew[grow + c0] = st;
                    float g0 = 1.f / (1.f + __expf(-ev0));
                    float g1 = 1.f / (1.f + __expf(-ev1));
                    s[nt][0] += ev0;       s[nt][1] += ev1;
                    q[nt][0] += ev0 * ev0; q[nt][1] += ev1 * ev1;
                    ag[nt][0] += sVx[rr * SEW + c0] * g0;
                    ag[nt][1] += sVx[rr * SEW + c0 + 1] * g1;
                }
            }
        }
    }

    // reduce across gid lanes (xor 16/8/4 preserves tig)
    #pragma unroll
    for (int nt = 0; nt < 4; ++nt)
        #pragma unroll
        for (int c = 0; c < 2; ++c) {
            #pragma unroll
            for (int d = 16; d >= 4; d >>= 1) {
                s[nt][c]  += __shfl_xor_sync(0xffffffffu, s[nt][c],  d);
                q[nt][c]  += __shfl_xor_sync(0xffffffffu, q[nt][c],  d);
                ag[nt][c] += __shfl_xor_sync(0xffffffffu, ag[nt][c], d);
            }
        }
    if (gid == 0) {
        #pragma unroll
        for (int nt = 0; nt < 4; ++nt) {
            #pragma unroll
            for (int c = 0; c < 2; ++c) {
                int col = nq * 32 + nt * 8 + 2 * tig + c;
                atomicAdd(&sh_sum[col], s[nt][c]);
                atomicAdd(&sh_sq[col],  q[nt][c]);
                atomicAdd(&sh_agg[col], ag[nt][c]);
            }
        }
    }
    __syncthreads();
    if (tid < NH) {
        atomicAdd(&g_sum_e[tid], sh_sum[tid]);
        atomicAdd(&g_sq_e[tid],  sh_sq[tid]);
        atomicAdd(&g_agg[bi * NH + tid], sh_agg[tid]);
    }
}

// ---------------------------------------------------------------------------
// x path stats: partial per-channel sums of x_new = Ux + agg
// ---------------------------------------------------------------------------
__global__ void __launch_bounds__(128) xstats_kernel()
{
    int h = threadIdx.x;
    float s = 0.f, q = 0.f;
    for (int r = blockIdx.x; r < NBV; r += gridDim.x) {
        float v = g_lin[r * NH + h] + g_agg[r * NH + h];
        s += v; q += v * v;
    }
    atomicAdd(&g_xsum[h], s);
    atomicAdd(&g_xsq[h],  q);
}

// ---------------------------------------------------------------------------
// x path apply: BN + ReLU
// ---------------------------------------------------------------------------
__global__ void __launch_bounds__(256) xapply_kernel(
    const float* __restrict__ gx, const float* __restrict__ bx,
    float* __restrict__ xout)
{
    __shared__ float sc[NH], sh[NH];
    int tid = threadIdx.x;
    if (tid < NH) {
        float m   = g_xsum[tid] * (1.f / NBV);
        float var = g_xsq[tid]  * (1.f / NBV) - m * m;
        float scl = gx[tid] * rsqrtf(var + BN_EPS);
        sc[tid] = scl; sh[tid] = bx[tid] - m * scl;
    }
    __syncthreads();
    int stride = gridDim.x * blockDim.x;
    for (int i = blockIdx.x * blockDim.x + tid; i < NBV * NH; i += stride) {
        int h = i & 127;
        float v = g_lin[i] + g_agg[i];
        xout[i] = fmaxf(v * sc[h] + sh[h], 0.f);
    }
}

// ---------------------------------------------------------------------------
// e path: BN(e_new) + ReLU, in place over eout, float4
// ---------------------------------------------------------------------------
__global__ void __launch_bounds__(256) eout_kernel(
    const float* __restrict__ ge, const float* __restrict__ be,
    float* __restrict__ eout)
{
    __shared__ float scale[NH], shift[NH];
    int tid = threadIdx.x;
    if (tid < NH) {
        float m   = g_sum_e[tid] * (1.f / NBVV);
        float var = g_sq_e[tid]  * (1.f / NBVV) - m * m;
        float sc  = __ldg(&ge[tid]) * rsqrtf(var + BN_EPS);
        scale[tid] = sc; shift[tid] = __ldg(&be[tid]) - m * sc;
    }
    __syncthreads();
    float4* buf = (float4*)eout;
    int total = NBVV * NH / 4;                    // 10,240,000
    int stride = gridDim.x * blockDim.x;
    for (int i = blockIdx.x * blockDim.x + tid; i < total; i += stride) {
        float4 v = buf[i];
        int h = (i * 4) & 127;
        v.x = fmaxf(v.x * scale[h]     + shift[h],     0.f);
        v.y = fmaxf(v.y * scale[h + 1] + shift[h + 1], 0.f);
        v.z = fmaxf(v.z * scale[h + 2] + shift[h + 2], 0.f);
        v.w = fmaxf(v.w * scale[h + 3] + shift[h + 3], 0.f);
        buf[i] = v;
    }
}

// ---------------------------------------------------------------------------
extern "C" void kernel_launch(void* const* d_in, const int* in_sizes, int n_in,
                              void* d_out, int out_size)
{
    (void)in_sizes; (void)n_in; (void)out_size;
    const float* x  = (const float*)d_in[0];
    const float* e  = (const float*)d_in[1];
    // d_in[2] = graph (unused by reference)
    const float* Uw = (const float*)d_in[3];  const float* Ub = (const float*)d_in[4];
    const float* Vw = (const float*)d_in[5];  const float* Vb = (const float*)d_in[6];
    const float* Aw = (const float*)d_in[7];  const float* Ab = (const float*)d_in[8];
    const float* Bw = (const float*)d_in[9];  const float* Bb = (const float*)d_in[10];
    const float* Cw = (const float*)d_in[11]; const float* Cb = (const float*)d_in[12];
    const float* gx = (const float*)d_in[13]; const float* bx = (const float*)d_in[14];
    const float* ge = (const float*)d_in[15]; const float* be = (const float*)d_in[16];

    float* xout = (float*)d_out;               // (B,V,H)   = 102400 floats
    float* eout = xout + NBV * NH;             // (B,V,V,H) = 40,960,000 floats

    const int smem_bytes = (64 * SEW + 128 * SEW + 5 * NH) * 4;   // ~104 KB
    static int attr_done = 0;
    if (!attr_done) {
        cudaFuncSetAttribute(egemm_mma_kernel,
                             cudaFuncAttributeMaxDynamicSharedMemorySize, smem_bytes);
        attr_done = 1;
    }

    zero_kernel<<<(NBV * NH + 255) / 256, 256>>>();

    LinParams p;
    p.W0 = Uw; p.W1 = Vw; p.W2 = Aw; p.W3 = Bw;
    p.b0 = Ub; p.b1 = Vb; p.b2 = Ab; p.b3 = Bb;
    lin4_kernel<<<dim3(NBV / 80, 4), 256>>>(x, p);

    egemm_mma_kernel<<<dim3((NV + BJ - 1) / BJ, NBV), 256, smem_bytes>>>(e, Cw, Cb, eout);

    xstats_kernel<<<64, 128>>>();
    xapply_kernel<<<100, 256>>>(gx, bx, xout);
    eout_kernel<<<3072, 256>>>(ge, be, eout);
}

// round 11
// speedup vs baseline: 1.0748x; 1.0654x over previous
#include <cuda_runtime.h>
#include <math.h>
#include <stdint.h>

#define NB   2
#define NV   400
#define NH   128
#define NBV  800          // B*V
#define NBVV 320000       // B*V*V
#define BJ   64           // j rows per block in egemm
#define BN_EPS 1e-5f
#define SEW 132           // padded row stride (u32 words) for 128-wide tiles

// ---- scratch (device globals; no allocation allowed) ----
__device__ __align__(16) float    g_lin[4 * NBV * NH];  // [0]=Ux [1]=Vx [2]=Ax [3]=Bx
__device__ __align__(16) float    g_agg[NBV * NH];      // sum_j Vx*gate
__device__ __align__(16) uint32_t g_cwt[NH * NH];       // tf32-converted Cw
__device__ float g_sum_e[NH];
__device__ float g_sq_e[NH];
__device__ float g_xsum[NH];
__device__ float g_xsq[NH];

struct LinParams {
    const float *W0, *W1, *W2, *W3;
    const float *b0, *b1, *b2, *b3;
};

__device__ __forceinline__ uint32_t f2tf32(float f) {
    uint32_t u;
    asm("cvt.rna.tf32.f32 %0, %1;" : "=r"(u) : "f"(f));
    return u;
}

#define MMA_TF32(d, a, b0v, b1v)                                             \
    asm volatile(                                                            \
        "mma.sync.aligned.m16n8k8.row.col.f32.tf32.tf32.f32 "                \
        "{%0,%1,%2,%3}, {%4,%5,%6,%7}, {%8,%9}, {%0,%1,%2,%3};"              \
        : "+f"((d)[0]), "+f"((d)[1]), "+f"((d)[2]), "+f"((d)[3])             \
        : "r"((a)[0]), "r"((a)[1]), "r"((a)[2]), "r"((a)[3]),                \
          "r"(b0v), "r"(b1v))

// ---------------------------------------------------------------------------
// zero accumulators + pre-convert Cw to tf32
// ---------------------------------------------------------------------------
__global__ void zero_kernel(const float* __restrict__ Cw) {
    int i = blockIdx.x * blockDim.x + threadIdx.x;
    if (i < NBV * NH) g_agg[i] = 0.f;
    if (i < NH * NH)  g_cwt[i] = f2tf32(Cw[i]);
    if (i < NH) {
        g_sum_e[i] = 0.f; g_sq_e[i] = 0.f;
        g_xsum[i] = 0.f;  g_xsq[i] = 0.f;
    }
}

// ---------------------------------------------------------------------------
// four small linears: y = x @ W^T + b   (M=800, K=N=128, z selects matrix)
// ---------------------------------------------------------------------------
__global__ void __launch_bounds__(256) lin4_kernel(const float* __restrict__ x, LinParams p)
{
    __shared__ float As[80][33];
    __shared__ float Bs[32][NH + 4];
    int tid = threadIdx.x;
    int tx = tid & 15, ty = tid >> 4;
    int z = blockIdx.y;
    const float* W; const float* bias;
    if (z == 0)      { W = p.W0; bias = p.b0; }
    else if (z == 1) { W = p.W1; bias = p.b1; }
    else if (z == 2) { W = p.W2; bias = p.b2; }
    else             { W = p.W3; bias = p.b3; }
    int r0 = blockIdx.x * 80;
    const float* Arow = x + r0 * NH;

    float acc[5][8];
    #pragma unroll
    for (int s = 0; s < 5; ++s)
        #pragma unroll
        for (int c = 0; c < 8; ++c) acc[s][c] = 0.f;

    for (int kc = 0; kc < NH; kc += 32) {
        #pragma unroll
        for (int it = 0; it < 10; ++it) {
            int idx = tid + it * 256;
            int r = idx >> 5, k = idx & 31;
            As[r][k] = Arow[r * NH + kc + k];
        }
        #pragma unroll
        for (int it = 0; it < 16; ++it) {
            int idx = tid + it * 256;
            int n = idx >> 5, k = idx & 31;
            Bs[k][n] = W[n * NH + kc + k];
        }
        __syncthreads();
        #pragma unroll
        for (int k = 0; k < 32; ++k) {
            float a[5];
            #pragma unroll
            for (int s = 0; s < 5; ++s) a[s] = As[ty + 16 * s][k];
            float4 u = *(const float4*)&Bs[k][4 * tx];
            float4 w = *(const float4*)&Bs[k][64 + 4 * tx];
            #pragma unroll
            for (int s = 0; s < 5; ++s) {
                acc[s][0] += a[s] * u.x; acc[s][1] += a[s] * u.y;
                acc[s][2] += a[s] * u.z; acc[s][3] += a[s] * u.w;
                acc[s][4] += a[s] * w.x; acc[s][5] += a[s] * w.y;
                acc[s][6] += a[s] * w.z; acc[s][7] += a[s] * w.w;
            }
        }
        __syncthreads();
    }

    int n0 = 4 * tx, n1 = 64 + 4 * tx;
    float cb[8];
    *(float4*)&cb[0] = *(const float4*)&bias[n0];
    *(float4*)&cb[4] = *(const float4*)&bias[n1];
    float* out = g_lin + z * NBV * NH;
    #pragma unroll
    for (int s = 0; s < 5; ++s) {
        int r = r0 + ty + 16 * s;
        float ov[8];
        #pragma unroll
        for (int c = 0; c < 8; ++c) ov[c] = acc[s][c] + cb[c];
        *(float4*)&out[r * NH + n0] = *(float4*)&ov[0];
        *(float4*)&out[r * NH + n1] = *(float4*)&ov[4];
    }
}

// ---------------------------------------------------------------------------
// tf32 tensor-core fused kernel, two modes:
//   APPLY=0 (stats): Ce GEMM -> e_new in regs -> per-channel sum/sumsq + agg
//   APPLY=1 (apply): Ce GEMM (recompute) -> BN apply + ReLU -> store eout
// grid: (7, 800), block 256 (8 warps); warp w: mq=w>>2, nq=w&3
// ---------------------------------------------------------------------------
template <int APPLY>
__global__ void __launch_bounds__(256) egemm_kernel(
    const float* __restrict__ e, const float* __restrict__ Cb,
    const float* __restrict__ ge, const float* __restrict__ be,
    float* __restrict__ eout)
{
    extern __shared__ uint32_t dyn[];
    uint32_t* sE = dyn;                    // [64][SEW] tf32
    uint32_t* sB = dyn + 64 * SEW;         // [128][SEW] tf32
    float* aux   = (float*)(dyn + 64 * SEW + 128 * SEW);
    // stats mode: sum/sq/agg partials; apply mode: scale/shift
    float* sh_sum = aux;                   // [128]  (apply: scE)
    float* sh_sq  = aux + NH;              // [128]  (apply: shE)
    float* sh_agg = aux + 2 * NH;          // [128]
    float* cbS    = aux + 3 * NH;          // [128]
    float* bxS    = aux + 4 * NH;          // [128]
    // phase-3 reuse of tile space:
    float* sAx = (float*)dyn;              // [64][SEW]
    float* sVx = (float*)(dyn + 64 * SEW); // [64][SEW] (stats only)

    int tid  = threadIdx.x;
    int lane = tid & 31;
    int wid  = tid >> 5;
    int gid  = lane >> 2, tig = lane & 3;
    int mq = wid >> 2;        // 0..1
    int nq = wid & 3;         // 0..3

    int bi = blockIdx.y;              // b*V + i
    int b  = bi / NV;
    int j0 = blockIdx.x * BJ;
    int rows = NV - j0; if (rows > BJ) rows = BJ;

    // ---- phase 1: stage E (tf32 cvt), pre-converted Cw, bias/Bx, mode data ----
    const float* Erow = e + ((size_t)bi * NV + j0) * NH;
    #pragma unroll
    for (int it = 0; it < 8; ++it) {
        int idx = tid + it * 256;         // 64*32
        int r = idx >> 5, c4 = (idx & 31) * 4;
        float4 v = make_float4(0.f, 0.f, 0.f, 0.f);
        if (r < rows) v = *(const float4*)&Erow[r * NH + c4];
        uint32_t* d = &sE[r * SEW + c4];
        d[0] = f2tf32(v.x); d[1] = f2tf32(v.y); d[2] = f2tf32(v.z); d[3] = f2tf32(v.w);
    }
    #pragma unroll
    for (int it = 0; it < 16; ++it) {
        int idx = tid + it * 256;         // 128*32
        int r = idx >> 5, c4 = (idx & 31) * 4;
        *(uint4*)&sB[r * SEW + c4] = *(const uint4*)&g_cwt[r * NH + c4];
    }
    if (tid < NH) {
        cbS[tid] = Cb[tid];
        bxS[tid] = g_lin[3 * NBV * NH + bi * NH + tid];   // Bx row
        if (APPLY) {
            float m   = g_sum_e[tid] * (1.f / NBVV);
            float var = g_sq_e[tid]  * (1.f / NBVV) - m * m;
            float sc  = ge[tid] * rsqrtf(var + BN_EPS);
            sh_sum[tid] = sc;                       // scE
            sh_sq[tid]  = be[tid] - m * sc;         // shE
        } else {
            sh_sum[tid] = 0.f; sh_sq[tid] = 0.f; sh_agg[tid] = 0.f;
        }
    }
    __syncthreads();

    // ---- phase 2: mma mainloop, K=128 in 16 steps of 8 ----
    float acc[2][4][4];
    #pragma unroll
    for (int mt = 0; mt < 2; ++mt)
        #pragma unroll
        for (int nt = 0; nt < 4; ++nt)
            #pragma unroll
            for (int c = 0; c < 4; ++c) acc[mt][nt][c] = 0.f;

    #pragma unroll
    for (int k0 = 0; k0 < NH; k0 += 8) {
        uint32_t a[2][4];
        #pragma unroll
        for (int mt = 0; mt < 2; ++mt) {
            int r = mq * 32 + mt * 16 + gid;
            a[mt][0] = sE[r * SEW + k0 + tig];
            a[mt][1] = sE[(r + 8) * SEW + k0 + tig];
            a[mt][2] = sE[r * SEW + k0 + tig + 4];
            a[mt][3] = sE[(r + 8) * SEW + k0 + tig + 4];
        }
        #pragma unroll
        for (int nt = 0; nt < 4; ++nt) {
            int n = nq * 32 + nt * 8 + gid;
            uint32_t b0 = sB[n * SEW + k0 + tig];
            uint32_t b1 = sB[n * SEW + k0 + tig + 4];
            MMA_TF32(acc[0][nt], a[0], b0, b1);
            MMA_TF32(acc[1][nt], a[1], b0, b1);
        }
    }
    __syncthreads();

    // ---- phase 3: stage Ax (both) and Vx (stats only) into reused smem ----
    const float* AxG = g_lin + 2 * NBV * NH;
    const float* VxG = g_lin + 1 * NBV * NH;
    #pragma unroll
    for (int it = 0; it < 8; ++it) {
        int idx = tid + it * 256;
        int r = idx >> 5, c4 = (idx & 31) * 4;
        float4 av = make_float4(0.f, 0.f, 0.f, 0.f);
        float4 vv = av;
        if (r < rows) {
            size_t base = ((size_t)(b * NV + j0 + r)) * NH + c4;
            av = *(const float4*)&AxG[base];
            if (!APPLY) vv = *(const float4*)&VxG[base];
        }
        *(float4*)&sAx[r * SEW + c4] = av;
        if (!APPLY) *(float4*)&sVx[r * SEW + c4] = vv;
    }
    __syncthreads();

    // ---- phase 4: epilogue ----
    if (APPLY) {
        #pragma unroll
        for (int mt = 0; mt < 2; ++mt) {
            #pragma unroll
            for (int half = 0; half < 2; ++half) {
                int rr = mq * 32 + mt * 16 + half * 8 + gid;
                if (rr < rows) {
                    size_t grow = ((size_t)bi * NV + j0 + rr) * NH;
                    #pragma unroll
                    for (int nt = 0; nt < 4; ++nt) {
                        int c0 = nq * 32 + nt * 8 + 2 * tig;
                        float ev0 = acc[mt][nt][half * 2]     + cbS[c0]     + sAx[rr * SEW + c0]     + bxS[c0];
                        float ev1 = acc[mt][nt][half * 2 + 1] + cbS[c0 + 1] + sAx[rr * SEW + c0 + 1] + bxS[c0 + 1];
                        float2 st;
                        st.x = fmaxf(ev0 * sh_sum[c0]     + sh_sq[c0],     0.f);
                        st.y = fmaxf(ev1 * sh_sum[c0 + 1] + sh_sq[c0 + 1], 0.f);
                        *(float2*)&eout[grow + c0] = st;
                    }
                }
            }
        }
    } else {
        float s[4][2], q[4][2], ag[4][2];
        #pragma unroll
        for (int nt = 0; nt < 4; ++nt)
            #pragma unroll
            for (int c = 0; c < 2; ++c) { s[nt][c] = 0.f; q[nt][c] = 0.f; ag[nt][c] = 0.f; }

        #pragma unroll
        for (int mt = 0; mt < 2; ++mt) {
            #pragma unroll
            for (int half = 0; half < 2; ++half) {
                int rr = mq * 32 + mt * 16 + half * 8 + gid;
                if (rr < rows) {
                    #pragma unroll
                    for (int nt = 0; nt < 4; ++nt) {
                        int c0 = nq * 32 + nt * 8 + 2 * tig;
                        float ev0 = acc[mt][nt][half * 2]     + cbS[c0]     + sAx[rr * SEW + c0]     + bxS[c0];
                        float ev1 = acc[mt][nt][half * 2 + 1] + cbS[c0 + 1] + sAx[rr * SEW + c0 + 1] + bxS[c0 + 1];
                        float g0 = 1.f / (1.f + __expf(-ev0));
                        float g1 = 1.f / (1.f + __expf(-ev1));
                        s[nt][0] += ev0;       s[nt][1] += ev1;
                        q[nt][0] += ev0 * ev0; q[nt][1] += ev1 * ev1;
                        ag[nt][0] += sVx[rr * SEW + c0] * g0;
                        ag[nt][1] += sVx[rr * SEW + c0 + 1] * g1;
                    }
                }
            }
        }
        // reduce across gid lanes (xor 16/8/4 preserves tig)
        #pragma unroll
        for (int nt = 0; nt < 4; ++nt)
            #pragma unroll
            for (int c = 0; c < 2; ++c) {
                #pragma unroll
                for (int d = 16; d >= 4; d >>= 1) {
                    s[nt][c]  += __shfl_xor_sync(0xffffffffu, s[nt][c],  d);
                    q[nt][c]  += __shfl_xor_sync(0xffffffffu, q[nt][c],  d);
                    ag[nt][c] += __shfl_xor_sync(0xffffffffu, ag[nt][c], d);
                }
            }
        if (gid == 0) {
            #pragma unroll
            for (int nt = 0; nt < 4; ++nt)
                #pragma unroll
                for (int c = 0; c < 2; ++c) {
                    int col = nq * 32 + nt * 8 + 2 * tig + c;
                    atomicAdd(&sh_sum[col], s[nt][c]);
                    atomicAdd(&sh_sq[col],  q[nt][c]);
                    atomicAdd(&sh_agg[col], ag[nt][c]);
                }
        }
        __syncthreads();
        if (tid < NH) {
            atomicAdd(&g_sum_e[tid], sh_sum[tid]);
            atomicAdd(&g_sq_e[tid],  sh_sq[tid]);
            atomicAdd(&g_agg[bi * NH + tid], sh_agg[tid]);
        }
    }
}

// ---------------------------------------------------------------------------
// x path stats: partial per-channel sums of x_new = Ux + agg
// ---------------------------------------------------------------------------
__global__ void __launch_bounds__(128) xstats_kernel()
{
    int h = threadIdx.x;
    float s = 0.f, q = 0.f;
    for (int r = blockIdx.x; r < NBV; r += gridDim.x) {
        float v = g_lin[r * NH + h] + g_agg[r * NH + h];
        s += v; q += v * v;
    }
    atomicAdd(&g_xsum[h], s);
    atomicAdd(&g_xsq[h],  q);
}

// ---------------------------------------------------------------------------
// x path apply: BN + ReLU
// ---------------------------------------------------------------------------
__global__ void __launch_bounds__(256) xapply_kernel(
    const float* __restrict__ gx, const float* __restrict__ bx,
    float* __restrict__ xout)
{
    __shared__ float sc[NH], sh[NH];
    int tid = threadIdx.x;
    if (tid < NH) {
        float m   = g_xsum[tid] * (1.f / NBV);
        float var = g_xsq[tid]  * (1.f / NBV) - m * m;
        float scl = gx[tid] * rsqrtf(var + BN_EPS);
        sc[tid] = scl; sh[tid] = bx[tid] - m * scl;
    }
    __syncthreads();
    int stride = gridDim.x * blockDim.x;
    for (int i = blockIdx.x * blockDim.x + tid; i < NBV * NH; i += stride) {
        int h = i & 127;
        float v = g_lin[i] + g_agg[i];
        xout[i] = fmaxf(v * sc[h] + sh[h], 0.f);
    }
}

// ---------------------------------------------------------------------------
extern "C" void kernel_launch(void* const* d_in, const int* in_sizes, int n_in,
                              void* d_out, int out_size)
{
    (void)in_sizes; (void)n_in; (void)out_size;
    const float* x  = (const float*)d_in[0];
    const float* e  = (const float*)d_in[1];
    // d_in[2] = graph (unused by reference)
    const float* Uw = (const float*)d_in[3];  const float* Ub = (const float*)d_in[4];
    const float* Vw = (const float*)d_in[5];  const float* Vb = (const float*)d_in[6];
    const float* Aw = (const float*)d_in[7];  const float* Ab = (const float*)d_in[8];
    const float* Bw = (const float*)d_in[9];  const float* Bb = (const float*)d_in[10];
    const float* Cw = (const float*)d_in[11]; const float* Cb = (const float*)d_in[12];
    const float* gx = (const float*)d_in[13]; const float* bx = (const float*)d_in[14];
    const float* ge = (const float*)d_in[15]; const float* be = (const float*)d_in[16];

    float* xout = (float*)d_out;               // (B,V,H)   = 102400 floats
    float* eout = xout + NBV * NH;             // (B,V,V,H) = 40,960,000 floats

    const int smem_bytes = (64 * SEW + 128 * SEW + 5 * NH) * 4;   // ~104 KB
    static int attr_done = 0;
    if (!attr_done) {
        cudaFuncSetAttribute(egemm_kernel<0>,
                             cudaFuncAttributeMaxDynamicSharedMemorySize, smem_bytes);
        cudaFuncSetAttribute(egemm_kernel<1>,
                             cudaFuncAttributeMaxDynamicSharedMemorySize, smem_bytes);
        attr_done = 1;
    }

    zero_kernel<<<(NBV * NH + 255) / 256, 256>>>(Cw);

    LinParams p;
    p.W0 = Uw; p.W1 = Vw; p.W2 = Aw; p.W3 = Bw;
    p.b0 = Ub; p.b1 = Vb; p.b2 = Ab; p.b3 = Bb;
    lin4_kernel<<<dim3(NBV / 80, 4), 256>>>(x, p);

    egemm_kernel<0><<<dim3((NV + BJ - 1) / BJ, NBV), 256, smem_bytes>>>(e, Cb, ge, be, eout);
    egemm_kernel<1><<<dim3((NV + BJ - 1) / BJ, NBV), 256, smem_bytes>>>(e, Cb, ge, be, eout);

    xstats_kernel<<<400, 128>>>();
    xapply_kernel<<<100, 256>>>(gx, bx, xout);
}

// round 13
// speedup vs baseline: 1.1552x; 1.0748x over previous
#include <cuda_runtime.h>
#include <math.h>
#include <stdint.h>

#define NB   2
#define NV   400
#define NH   128
#define NBV  800          // B*V
#define NBVV 320000       // B*V*V
#define BJ   64           // j rows per block in egemm
#define BN_EPS 1e-5f
#define CK   64           // k-chunk width
#define CW   68           // padded chunk row stride in u32 words (68 mod 32 = 4)

// ---- scratch (device globals; no allocation allowed) ----
__device__ __align__(16) float    g_lin[4 * NBV * NH];  // [0]=Ux [1]=Vx [2]=Ax [3]=Bx
__device__ __align__(16) float    g_agg[NBV * NH];      // sum_j Vx*gate
__device__ __align__(16) uint32_t g_cwt[NH * NH];       // tf32-converted Cw
__device__ float g_sum_e[NH];
__device__ float g_sq_e[NH];
__device__ float g_xsum[NH];
__device__ float g_xsq[NH];

struct LinParams {
    const float *W0, *W1, *W2, *W3;
    const float *b0, *b1, *b2, *b3;
};

__device__ __forceinline__ uint32_t f2tf32(float f) {
    uint32_t u;
    asm("cvt.rna.tf32.f32 %0, %1;" : "=r"(u) : "f"(f));
    return u;
}

#define MMA_TF32(d, a, b0v, b1v)                                             \
    asm volatile(                                                            \
        "mma.sync.aligned.m16n8k8.row.col.f32.tf32.tf32.f32 "                \
        "{%0,%1,%2,%3}, {%4,%5,%6,%7}, {%8,%9}, {%0,%1,%2,%3};"              \
        : "+f"((d)[0]), "+f"((d)[1]), "+f"((d)[2]), "+f"((d)[3])             \
        : "r"((a)[0]), "r"((a)[1]), "r"((a)[2]), "r"((a)[3]),                \
          "r"(b0v), "r"(b1v))

// ---------------------------------------------------------------------------
// zero accumulators + pre-convert Cw to tf32
// ---------------------------------------------------------------------------
__global__ void zero_kernel(const float* __restrict__ Cw) {
    int i = blockIdx.x * blockDim.x + threadIdx.x;
    if (i < NBV * NH) g_agg[i] = 0.f;
    if (i < NH * NH)  g_cwt[i] = f2tf32(Cw[i]);
    if (i < NH) {
        g_sum_e[i] = 0.f; g_sq_e[i] = 0.f;
        g_xsum[i] = 0.f;  g_xsq[i] = 0.f;
    }
}

// ---------------------------------------------------------------------------
// four small linears: y = x @ W^T + b   (M=800, K=N=128, z selects matrix)
// ---------------------------------------------------------------------------
__global__ void __launch_bounds__(256) lin4_kernel(const float* __restrict__ x, LinParams p)
{
    __shared__ float As[80][33];
    __shared__ float Bs[32][NH + 4];
    int tid = threadIdx.x;
    int tx = tid & 15, ty = tid >> 4;
    int z = blockIdx.y;
    const float* W; const float* bias;
    if (z == 0)      { W = p.W0; bias = p.b0; }
    else if (z == 1) { W = p.W1; bias = p.b1; }
    else if (z == 2) { W = p.W2; bias = p.b2; }
    else             { W = p.W3; bias = p.b3; }
    int r0 = blockIdx.x * 80;
    const float* Arow = x + r0 * NH;

    float acc[5][8];
    #pragma unroll
    for (int s = 0; s < 5; ++s)
        #pragma unroll
        for (int c = 0; c < 8; ++c) acc[s][c] = 0.f;

    for (int kc = 0; kc < NH; kc += 32) {
        #pragma unroll
        for (int it = 0; it < 10; ++it) {
            int idx = tid + it * 256;
            int r = idx >> 5, k = idx & 31;
            As[r][k] = Arow[r * NH + kc + k];
        }
        #pragma unroll
        for (int it = 0; it < 16; ++it) {
            int idx = tid + it * 256;
            int n = idx >> 5, k = idx & 31;
            Bs[k][n] = W[n * NH + kc + k];
        }
        __syncthreads();
        #pragma unroll
        for (int k = 0; k < 32; ++k) {
            float a[5];
            #pragma unroll
            for (int s = 0; s < 5; ++s) a[s] = As[ty + 16 * s][k];
            float4 u = *(const float4*)&Bs[k][4 * tx];
            float4 w = *(const float4*)&Bs[k][64 + 4 * tx];
            #pragma unroll
            for (int s = 0; s < 5; ++s) {
                acc[s][0] += a[s] * u.x; acc[s][1] += a[s] * u.y;
                acc[s][2] += a[s] * u.z; acc[s][3] += a[s] * u.w;
                acc[s][4] += a[s] * w.x; acc[s][5] += a[s] * w.y;
                acc[s][6] += a[s] * w.z; acc[s][7] += a[s] * w.w;
            }
        }
        __syncthreads();
    }

    int n0 = 4 * tx, n1 = 64 + 4 * tx;
    float cb[8];
    *(float4*)&cb[0] = *(const float4*)&bias[n0];
    *(float4*)&cb[4] = *(const float4*)&bias[n1];
    float* out = g_lin + z * NBV * NH;
    #pragma unroll
    for (int s = 0; s < 5; ++s) {
        int r = r0 + ty + 16 * s;
        float ov[8];
        #pragma unroll
        for (int c = 0; c < 8; ++c) ov[c] = acc[s][c] + cb[c];
        *(float4*)&out[r * NH + n0] = *(float4*)&ov[0];
        *(float4*)&out[r * NH + n1] = *(float4*)&ov[4];
    }
}

// ---------------------------------------------------------------------------
// tf32 tensor-core fused kernel, k-chunked smem (54.8 KB -> 4 blocks/SM):
//   APPLY=0 (stats): Ce GEMM -> e_new in regs -> per-channel sum/sumsq + agg
//   APPLY=1 (apply): Ce GEMM (recompute) -> BN apply + ReLU -> store eout
// grid: (7, 800), block 256 (8 warps); warp w: mq=w>>2, nq=w&3
// ---------------------------------------------------------------------------
template <int APPLY>
__global__ void __launch_bounds__(256) egemm_kernel(
    const float* __restrict__ e, const float* __restrict__ Cb,
    const float* __restrict__ ge, const float* __restrict__ be,
    float* __restrict__ eout)
{
    extern __shared__ uint32_t dyn[];
    uint32_t* sE = dyn;                    // [64][CW] tf32 chunk
    uint32_t* sB = dyn + 64 * CW;          // [128][CW] tf32 chunk
    float* aux   = (float*)(dyn + 64 * CW + 128 * CW);
    float* sh_sum = aux;                   // [128] (apply: scE)
    float* sh_sq  = aux + NH;              // [128] (apply: shE)
    float* sh_agg = aux + 2 * NH;          // [128]
    float* cbS    = aux + 3 * NH;          // [128]
    float* bxS    = aux + 4 * NH;          // [128]

    int tid  = threadIdx.x;
    int lane = tid & 31;
    int wid  = tid >> 5;
    int gid  = lane >> 2, tig = lane & 3;
    int mq = wid >> 2;        // 0..1
    int nq = wid & 3;         // 0..3

    int bi = blockIdx.y;              // b*V + i
    int b  = bi / NV;
    int j0 = blockIdx.x * BJ;
    int rows = NV - j0; if (rows > BJ) rows = BJ;

    const float* Erow = e + ((size_t)bi * NV + j0) * NH;

    if (tid < NH) {
        cbS[tid] = Cb[tid];
        bxS[tid] = g_lin[3 * NBV * NH + bi * NH + tid];   // Bx row
        if (APPLY) {
            float m   = g_sum_e[tid] * (1.f / NBVV);
            float var = g_sq_e[tid]  * (1.f / NBVV) - m * m;
            float sc  = ge[tid] * rsqrtf(var + BN_EPS);
            sh_sum[tid] = sc;                       // scE
            sh_sq[tid]  = be[tid] - m * sc;         // shE
        } else {
            sh_sum[tid] = 0.f; sh_sq[tid] = 0.f; sh_agg[tid] = 0.f;
        }
    }

    float acc[2][4][4];
    #pragma unroll
    for (int mt = 0; mt < 2; ++mt)
        #pragma unroll
        for (int nt = 0; nt < 4; ++nt)
            #pragma unroll
            for (int c = 0; c < 4; ++c) acc[mt][nt][c] = 0.f;

    // ---- k-chunked mainloop: 2 chunks of 64 ----
    #pragma unroll
    for (int kc = 0; kc < NH; kc += CK) {
        // stage E chunk (64 rows x 64 cols, cvt to tf32)
        #pragma unroll
        for (int it = 0; it < 4; ++it) {
            int idx = tid + it * 256;           // 0..1023
            int r = idx >> 4, c4 = (idx & 15) * 4;
            float4 v = make_float4(0.f, 0.f, 0.f, 0.f);
            if (r < rows) v = *(const float4*)&Erow[r * NH + kc + c4];
            uint32_t* d = &sE[r * CW + c4];
            d[0] = f2tf32(v.x); d[1] = f2tf32(v.y);
            d[2] = f2tf32(v.z); d[3] = f2tf32(v.w);
        }
        // stage Cw chunk (128 rows x 64 cols, pre-converted)
        #pragma unroll
        for (int it = 0; it < 8; ++it) {
            int idx = tid + it * 256;           // 0..2047
            int r = idx >> 4, c4 = (idx & 15) * 4;
            *(uint4*)&sB[r * CW + c4] = *(const uint4*)&g_cwt[r * NH + kc + c4];
        }
        __syncthreads();

        #pragma unroll
        for (int k0 = 0; k0 < CK; k0 += 8) {
            uint32_t a[2][4];
            #pragma unroll
            for (int mt = 0; mt < 2; ++mt) {
                int r = mq * 32 + mt * 16 + gid;
                a[mt][0] = sE[r * CW + k0 + tig];
                a[mt][1] = sE[(r + 8) * CW + k0 + tig];
                a[mt][2] = sE[r * CW + k0 + tig + 4];
                a[mt][3] = sE[(r + 8) * CW + k0 + tig + 4];
            }
            #pragma unroll
            for (int nt = 0; nt < 4; ++nt) {
                int n = nq * 32 + nt * 8 + gid;
                uint32_t b0 = sB[n * CW + k0 + tig];
                uint32_t b1 = sB[n * CW + k0 + tig + 4];
                MMA_TF32(acc[0][nt], a[0], b0, b1);
                MMA_TF32(acc[1][nt], a[1], b0, b1);
            }
        }
        __syncthreads();
    }

    // ---- epilogue (Ax/Vx read directly from global; L1/L2 absorb reuse) ----
    const float* AxG = g_lin + 2 * NBV * NH;
    const float* VxG = g_lin + 1 * NBV * NH;

    if (APPLY) {
        #pragma unroll
        for (int mt = 0; mt < 2; ++mt) {
            #pragma unroll
            for (int half = 0; half < 2; ++half) {
                int rr = mq * 32 + mt * 16 + half * 8 + gid;
                if (rr < rows) {
                    size_t xrow = ((size_t)(b * NV + j0 + rr)) * NH;
                    size_t grow = ((size_t)bi * NV + j0 + rr) * NH;
                    #pragma unroll
                    for (int nt = 0; nt < 4; ++nt) {
                        int c0 = nq * 32 + nt * 8 + 2 * tig;
                        float2 axv = __ldg((const float2*)&AxG[xrow + c0]);
                        float ev0 = acc[mt][nt][half * 2]     + cbS[c0]     + axv.x + bxS[c0];
                        float ev1 = acc[mt][nt][half * 2 + 1] + cbS[c0 + 1] + axv.y + bxS[c0 + 1];
                        float2 st;
                        st.x = fmaxf(ev0 * sh_sum[c0]     + sh_sq[c0],     0.f);
                        st.y = fmaxf(ev1 * sh_sum[c0 + 1] + sh_sq[c0 + 1], 0.f);
                        *(float2*)&eout[grow + c0] = st;
                    }
                }
            }
        }
    } else {
        float s[4][2], q[4][2], ag[4][2];
        #pragma unroll
        for (int nt = 0; nt < 4; ++nt)
            #pragma unroll
            for (int c = 0; c < 2; ++c) { s[nt][c] = 0.f; q[nt][c] = 0.f; ag[nt][c] = 0.f; }

        #pragma unroll
        for (int mt = 0; mt < 2; ++mt) {
            #pragma unroll
            for (int half = 0; half < 2; ++half) {
                int rr = mq * 32 + mt * 16 + half * 8 + gid;
                if (rr < rows) {
                    size_t xrow = ((size_t)(b * NV + j0 + rr)) * NH;
                    #pragma unroll
                    for (int nt = 0; nt < 4; ++nt) {
                        int c0 = nq * 32 + nt * 8 + 2 * tig;
                        float2 axv = __ldg((const float2*)&AxG[xrow + c0]);
                        float2 vxv = __ldg((const float2*)&VxG[xrow + c0]);
                        float ev0 = acc[mt][nt][half * 2]     + cbS[c0]     + axv.x + bxS[c0];
                        float ev1 = acc[mt][nt][half * 2 + 1] + cbS[c0 + 1] + axv.y + bxS[c0 + 1];
                        float g0 = 1.f / (1.f + __expf(-ev0));
                        float g1 = 1.f / (1.f + __expf(-ev1));
                        s[nt][0] += ev0;       s[nt][1] += ev1;
                        q[nt][0] += ev0 * ev0; q[nt][1] += ev1 * ev1;
                        ag[nt][0] += vxv.x * g0;
                        ag[nt][1] += vxv.y * g1;
                    }
                }
            }
        }
        // reduce across gid lanes (xor 16/8/4 preserves tig)
        #pragma unroll
        for (int nt = 0; nt < 4; ++nt)
            #pragma unroll
            for (int c = 0; c < 2; ++c) {
                #pragma unroll
                for (int d = 16; d >= 4; d >>= 1) {
                    s[nt][c]  += __shfl_xor_sync(0xffffffffu, s[nt][c],  d);
                    q[nt][c]  += __shfl_xor_sync(0xffffffffu, q[nt][c],  d);
                    ag[nt][c] += __shfl_xor_sync(0xffffffffu, ag[nt][c], d);
                }
            }
        if (gid == 0) {
            #pragma unroll
            for (int nt = 0; nt < 4; ++nt)
                #pragma unroll
                for (int c = 0; c < 2; ++c) {
                    int col = nq * 32 + nt * 8 + 2 * tig + c;
                    atomicAdd(&sh_sum[col], s[nt][c]);
                    atomicAdd(&sh_sq[col],  q[nt][c]);
                    atomicAdd(&sh_agg[col], ag[nt][c]);
                }
        }
        __syncthreads();
        if (tid < NH) {
            atomicAdd(&g_sum_e[tid], sh_sum[tid]);
            atomicAdd(&g_sq_e[tid],  sh_sq[tid]);
            atomicAdd(&g_agg[bi * NH + tid], sh_agg[tid]);
        }
    }
}

// ---------------------------------------------------------------------------
// x path stats: partial per-channel sums of x_new = Ux + agg
// ---------------------------------------------------------------------------
__global__ void __launch_bounds__(128) xstats_kernel()
{
    int h = threadIdx.x;
    float s = 0.f, q = 0.f;
    for (int r = blockIdx.x; r < NBV; r += gridDim.x) {
        float v = g_lin[r * NH + h] + g_agg[r * NH + h];
        s += v; q += v * v;
    }
    atomicAdd(&g_xsum[h], s);
    atomicAdd(&g_xsq[h],  q);
}

// ---------------------------------------------------------------------------
// x path apply: BN + ReLU
// ---------------------------------------------------------------------------
__global__ void __launch_bounds__(256) xapply_kernel(
    const float* __restrict__ gx, const float* __restrict__ bx,
    float* __restrict__ xout)
{
    __shared__ float sc[NH], sh[NH];
    int tid = threadIdx.x;
    if (tid < NH) {
        float m   = g_xsum[tid] * (1.f / NBV);
        float var = g_xsq[tid]  * (1.f / NBV) - m * m;
        float scl = gx[tid] * rsqrtf(var + BN_EPS);
        sc[tid] = scl; sh[tid] = bx[tid] - m * scl;
    }
    __syncthreads();
    int stride = gridDim.x * blockDim.x;
    for (int i = blockIdx.x * blockDim.x + tid; i < NBV * NH; i += stride) {
        int h = i & 127;
        float v = g_lin[i] + g_agg[i];
        xout[i] = fmaxf(v * sc[h] + sh[h], 0.f);
    }
}

// ---------------------------------------------------------------------------
extern "C" void kernel_launch(void* const* d_in, const int* in_sizes, int n_in,
                              void* d_out, int out_size)
{
    (void)in_sizes; (void)n_in; (void)out_size;
    const float* x  = (const float*)d_in[0];
    const float* e  = (const float*)d_in[1];
    // d_in[2] = graph (unused by reference)
    const float* Uw = (const float*)d_in[3];  const float* Ub = (const float*)d_in[4];
    const float* Vw = (const float*)d_in[5];  const float* Vb = (const float*)d_in[6];
    const float* Aw = (const float*)d_in[7];  const float* Ab = (const float*)d_in[8];
    const float* Bw = (const float*)d_in[9];  const float* Bb = (const float*)d_in[10];
    const float* Cw = (const float*)d_in[11]; const float* Cb = (const float*)d_in[12];
    const float* gx = (const float*)d_in[13]; const float* bx = (const float*)d_in[14];
    const float* ge = (const float*)d_in[15]; const float* be = (const float*)d_in[16];

    float* xout = (float*)d_out;               // (B,V,H)   = 102400 floats
    float* eout = xout + NBV * NH;             // (B,V,V,H) = 40,960,000 floats

    const int smem_bytes = (64 * CW + 128 * CW + 5 * NH) * 4;   // 54,784 B
    static int attr_done = 0;
    if (!attr_done) {
        cudaFuncSetAttribute(egemm_kernel<0>,
                             cudaFuncAttributeMaxDynamicSharedMemorySize, smem_bytes);
        cudaFuncSetAttribute(egemm_kernel<1>,
                             cudaFuncAttributeMaxDynamicSharedMemorySize, smem_bytes);
        attr_done = 1;
    }

    zero_kernel<<<(NBV * NH + 255) / 256, 256>>>(Cw);

    LinParams p;
    p.W0 = Uw; p.W1 = Vw; p.W2 = Aw; p.W3 = Bw;
    p.b0 = Ub; p.b1 = Vb; p.b2 = Ab; p.b3 = Bb;
    lin4_kernel<<<dim3(NBV / 80, 4), 256>>>(x, p);

    egemm_kernel<0><<<dim3((NV + BJ - 1) / BJ, NBV), 256, smem_bytes>>>(e, Cb, ge, be, eout);
    egemm_kernel<1><<<dim3((NV + BJ - 1) / BJ, NBV), 256, smem_bytes>>>(e, Cb, ge, be, eout);

    xstats_kernel<<<400, 128>>>();
    xapply_kernel<<<100, 256>>>(gx, bx, xout);
}

// round 14
// speedup vs baseline: 1.2865x; 1.1137x over previous
#include <cuda_runtime.h>
#include <math.h>
#include <stdint.h>

#define NB   2
#define NV   400
#define NH   128
#define NBV  800          // B*V
#define NBVV 320000       // B*V*V
#define BJ   64           // j rows per block in egemm
#define BN_EPS 1e-5f
#define CK   64           // k-chunk width
#define CW   68           // padded chunk row stride in u32 words (68 mod 32 = 4)

// ---- scratch (device globals; no allocation allowed) ----
__device__ __align__(16) float    g_lin[4 * NBV * NH];  // [0]=Ux [1]=Vx [2]=Ax [3]=Bx
__device__ __align__(16) float    g_agg[NBV * NH];      // sum_j Vx*gate
__device__ __align__(16) uint32_t g_cwt[NH * NH];       // tf32-converted Cw
__device__ float g_sum_e[NH];
__device__ float g_sq_e[NH];
__device__ float g_xsum[NH];
__device__ float g_xsq[NH];

struct LinParams {
    const float *W0, *W1, *W2, *W3;
    const float *b0, *b1, *b2, *b3;
};

__device__ __forceinline__ uint32_t f2tf32(float f) {
    uint32_t u;
    asm("cvt.rna.tf32.f32 %0, %1;" : "=r"(u) : "f"(f));
    return u;
}

#define MMA_TF32(d, a, b0v, b1v)                                             \
    asm volatile(                                                            \
        "mma.sync.aligned.m16n8k8.row.col.f32.tf32.tf32.f32 "                \
        "{%0,%1,%2,%3}, {%4,%5,%6,%7}, {%8,%9}, {%0,%1,%2,%3};"              \
        : "+f"((d)[0]), "+f"((d)[1]), "+f"((d)[2]), "+f"((d)[3])             \
        : "r"((a)[0]), "r"((a)[1]), "r"((a)[2]), "r"((a)[3]),                \
          "r"(b0v), "r"(b1v))

// ---------------------------------------------------------------------------
// zero accumulators + pre-convert Cw to tf32
// ---------------------------------------------------------------------------
__global__ void zero_kernel(const float* __restrict__ Cw) {
    int i = blockIdx.x * blockDim.x + threadIdx.x;
    if (i < NBV * NH) g_agg[i] = 0.f;
    if (i < NH * NH)  g_cwt[i] = f2tf32(Cw[i]);
    if (i < NH) {
        g_sum_e[i] = 0.f; g_sq_e[i] = 0.f;
        g_xsum[i] = 0.f;  g_xsq[i] = 0.f;
    }
}

// ---------------------------------------------------------------------------
// four small linears: y = x @ W^T + b   (M=800, K=N=128, z selects matrix)
// ---------------------------------------------------------------------------
__global__ void __launch_bounds__(256) lin4_kernel(const float* __restrict__ x, LinParams p)
{
    __shared__ float As[80][33];
    __shared__ float Bs[32][NH + 4];
    int tid = threadIdx.x;
    int tx = tid & 15, ty = tid >> 4;
    int z = blockIdx.y;
    const float* W; const float* bias;
    if (z == 0)      { W = p.W0; bias = p.b0; }
    else if (z == 1) { W = p.W1; bias = p.b1; }
    else if (z == 2) { W = p.W2; bias = p.b2; }
    else             { W = p.W3; bias = p.b3; }
    int r0 = blockIdx.x * 80;
    const float* Arow = x + r0 * NH;

    float acc[5][8];
    #pragma unroll
    for (int s = 0; s < 5; ++s)
        #pragma unroll
        for (int c = 0; c < 8; ++c) acc[s][c] = 0.f;

    for (int kc = 0; kc < NH; kc += 32) {
        #pragma unroll
        for (int it = 0; it < 10; ++it) {
            int idx = tid + it * 256;
            int r = idx >> 5, k = idx & 31;
            As[r][k] = Arow[r * NH + kc + k];
        }
        #pragma unroll
        for (int it = 0; it < 16; ++it) {
            int idx = tid + it * 256;
            int n = idx >> 5, k = idx & 31;
            Bs[k][n] = W[n * NH + kc + k];
        }
        __syncthreads();
        #pragma unroll
        for (int k = 0; k < 32; ++k) {
            float a[5];
            #pragma unroll
            for (int s = 0; s < 5; ++s) a[s] = As[ty + 16 * s][k];
            float4 u = *(const float4*)&Bs[k][4 * tx];
            float4 w = *(const float4*)&Bs[k][64 + 4 * tx];
            #pragma unroll
            for (int s = 0; s < 5; ++s) {
                acc[s][0] += a[s] * u.x; acc[s][1] += a[s] * u.y;
                acc[s][2] += a[s] * u.z; acc[s][3] += a[s] * u.w;
                acc[s][4] += a[s] * w.x; acc[s][5] += a[s] * w.y;
                acc[s][6] += a[s] * w.z; acc[s][7] += a[s] * w.w;
            }
        }
        __syncthreads();
    }

    int n0 = 4 * tx, n1 = 64 + 4 * tx;
    float cb[8];
    *(float4*)&cb[0] = *(const float4*)&bias[n0];
    *(float4*)&cb[4] = *(const float4*)&bias[n1];
    float* out = g_lin + z * NBV * NH;
    #pragma unroll
    for (int s = 0; s < 5; ++s) {
        int r = r0 + ty + 16 * s;
        float ov[8];
        #pragma unroll
        for (int c = 0; c < 8; ++c) ov[c] = acc[s][c] + cb[c];
        *(float4*)&out[r * NH + n0] = *(float4*)&ov[0];
        *(float4*)&out[r * NH + n1] = *(float4*)&ov[4];
    }
}

// ---------------------------------------------------------------------------
// tf32 tensor-core fused kernel, k-chunked smem (54.8 KB), forced 3 blocks/SM:
//   APPLY=0 (stats): Ce GEMM -> e_new in regs -> per-channel sum/sumsq + agg
//   APPLY=1 (apply): Ce GEMM (recompute) -> BN apply + ReLU -> store eout
// grid: (7, 800), block 256 (8 warps); warp w: mq=w>>2, nq=w&3
// ---------------------------------------------------------------------------
template <int APPLY>
__global__ void __launch_bounds__(256, 3) egemm_kernel(
    const float* __restrict__ e, const float* __restrict__ Cb,
    const float* __restrict__ ge, const float* __restrict__ be,
    float* __restrict__ eout)
{
    extern __shared__ uint32_t dyn[];
    uint32_t* sE = dyn;                    // [64][CW] tf32 chunk
    uint32_t* sB = dyn + 64 * CW;          // [128][CW] tf32 chunk
    float* aux   = (float*)(dyn + 64 * CW + 128 * CW);
    float* sh_sum = aux;                   // [128] (apply: scE)
    float* sh_sq  = aux + NH;              // [128] (apply: shE)
    float* sh_agg = aux + 2 * NH;          // [128]
    float* cbS    = aux + 3 * NH;          // [128]
    float* bxS    = aux + 4 * NH;          // [128]

    int tid  = threadIdx.x;
    int lane = tid & 31;
    int wid  = tid >> 5;
    int gid  = lane >> 2, tig = lane & 3;
    int mq = wid >> 2;        // 0..1
    int nq = wid & 3;         // 0..3

    int bi = blockIdx.y;              // b*V + i
    int b  = bi / NV;
    int j0 = blockIdx.x * BJ;
    int rows = NV - j0; if (rows > BJ) rows = BJ;

    const float* Erow = e + ((size_t)bi * NV + j0) * NH;

    if (tid < NH) {
        cbS[tid] = Cb[tid];
        bxS[tid] = g_lin[3 * NBV * NH + bi * NH + tid];   // Bx row
        if (APPLY) {
            float m   = g_sum_e[tid] * (1.f / NBVV);
            float var = g_sq_e[tid]  * (1.f / NBVV) - m * m;
            float sc  = ge[tid] * rsqrtf(var + BN_EPS);
            sh_sum[tid] = sc;                       // scE
            sh_sq[tid]  = be[tid] - m * sc;         // shE
        } else {
            sh_sum[tid] = 0.f; sh_sq[tid] = 0.f; sh_agg[tid] = 0.f;
        }
    }

    float acc[2][4][4];
    #pragma unroll
    for (int mt = 0; mt < 2; ++mt)
        #pragma unroll
        for (int nt = 0; nt < 4; ++nt)
            #pragma unroll
            for (int c = 0; c < 4; ++c) acc[mt][nt][c] = 0.f;

    // ---- k-chunked mainloop: 2 chunks of 64 ----
    #pragma unroll
    for (int kc = 0; kc < NH; kc += CK) {
        // stage E chunk (64 rows x 64 cols, cvt to tf32)
        #pragma unroll
        for (int it = 0; it < 4; ++it) {
            int idx = tid + it * 256;           // 0..1023
            int r = idx >> 4, c4 = (idx & 15) * 4;
            float4 v = make_float4(0.f, 0.f, 0.f, 0.f);
            if (r < rows) v = *(const float4*)&Erow[r * NH + kc + c4];
            uint32_t* d = &sE[r * CW + c4];
            d[0] = f2tf32(v.x); d[1] = f2tf32(v.y);
            d[2] = f2tf32(v.z); d[3] = f2tf32(v.w);
        }
        // stage Cw chunk (128 rows x 64 cols, pre-converted)
        #pragma unroll
        for (int it = 0; it < 8; ++it) {
            int idx = tid + it * 256;           // 0..2047
            int r = idx >> 4, c4 = (idx & 15) * 4;
            *(uint4*)&sB[r * CW + c4] = *(const uint4*)&g_cwt[r * NH + kc + c4];
        }
        __syncthreads();

        #pragma unroll
        for (int k0 = 0; k0 < CK; k0 += 8) {
            uint32_t a[2][4];
            #pragma unroll
            for (int mt = 0; mt < 2; ++mt) {
                int r = mq * 32 + mt * 16 + gid;
                a[mt][0] = sE[r * CW + k0 + tig];
                a[mt][1] = sE[(r + 8) * CW + k0 + tig];
                a[mt][2] = sE[r * CW + k0 + tig + 4];
                a[mt][3] = sE[(r + 8) * CW + k0 + tig + 4];
            }
            #pragma unroll
            for (int nt = 0; nt < 4; ++nt) {
                int n = nq * 32 + nt * 8 + gid;
                uint32_t b0 = sB[n * CW + k0 + tig];
                uint32_t b1 = sB[n * CW + k0 + tig + 4];
                MMA_TF32(acc[0][nt], a[0], b0, b1);
                MMA_TF32(acc[1][nt], a[1], b0, b1);
            }
        }
        __syncthreads();
    }

    // ---- epilogue (Ax/Vx read directly from global; L1/L2 absorb reuse) ----
    const float* AxG = g_lin + 2 * NBV * NH;
    const float* VxG = g_lin + 1 * NBV * NH;

    if (APPLY) {
        #pragma unroll
        for (int mt = 0; mt < 2; ++mt) {
            #pragma unroll
            for (int half = 0; half < 2; ++half) {
                int rr = mq * 32 + mt * 16 + half * 8 + gid;
                if (rr < rows) {
                    size_t xrow = ((size_t)(b * NV + j0 + rr)) * NH;
                    size_t grow = ((size_t)bi * NV + j0 + rr) * NH;
                    #pragma unroll
                    for (int nt = 0; nt < 4; ++nt) {
                        int c0 = nq * 32 + nt * 8 + 2 * tig;
                        float2 axv = __ldg((const float2*)&AxG[xrow + c0]);
                        float ev0 = acc[mt][nt][half * 2]     + cbS[c0]     + axv.x + bxS[c0];
                        float ev1 = acc[mt][nt][half * 2 + 1] + cbS[c0 + 1] + axv.y + bxS[c0 + 1];
                        float2 st;
                        st.x = fmaxf(ev0 * sh_sum[c0]     + sh_sq[c0],     0.f);
                        st.y = fmaxf(ev1 * sh_sum[c0 + 1] + sh_sq[c0 + 1], 0.f);
                        *(float2*)&eout[grow + c0] = st;
                    }
                }
            }
        }
    } else {
        float s[4][2], q[4][2], ag[4][2];
        #pragma unroll
        for (int nt = 0; nt < 4; ++nt)
            #pragma unroll
            for (int c = 0; c < 2; ++c) { s[nt][c] = 0.f; q[nt][c] = 0.f; ag[nt][c] = 0.f; }

        #pragma unroll
        for (int mt = 0; mt < 2; ++mt) {
            #pragma unroll
            for (int half = 0; half < 2; ++half) {
                int rr = mq * 32 + mt * 16 + half * 8 + gid;
                if (rr < rows) {
                    size_t xrow = ((size_t)(b * NV + j0 + rr)) * NH;
                    #pragma unroll
                    for (int nt = 0; nt < 4; ++nt) {
                        int c0 = nq * 32 + nt * 8 + 2 * tig;
                        float2 axv = __ldg((const float2*)&AxG[xrow + c0]);
                        float2 vxv = __ldg((const float2*)&VxG[xrow + c0]);
                        float ev0 = acc[mt][nt][half * 2]     + cbS[c0]     + axv.x + bxS[c0];
                        float ev1 = acc[mt][nt][half * 2 + 1] + cbS[c0 + 1] + axv.y + bxS[c0 + 1];
                        float g0 = 1.f / (1.f + __expf(-ev0));
                        float g1 = 1.f / (1.f + __expf(-ev1));
                        s[nt][0] += ev0;       s[nt][1] += ev1;
                        q[nt][0] += ev0 * ev0; q[nt][1] += ev1 * ev1;
                        ag[nt][0] += vxv.x * g0;
                        ag[nt][1] += vxv.y * g1;
                    }
                }
            }
        }
        // reduce across gid lanes (xor 16/8/4 preserves tig)
        #pragma unroll
        for (int nt = 0; nt < 4; ++nt)
            #pragma unroll
            for (int c = 0; c < 2; ++c) {
                #pragma unroll
                for (int d = 16; d >= 4; d >>= 1) {
                    s[nt][c]  += __shfl_xor_sync(0xffffffffu, s[nt][c],  d);
                    q[nt][c]  += __shfl_xor_sync(0xffffffffu, q[nt][c],  d);
                    ag[nt][c] += __shfl_xor_sync(0xffffffffu, ag[nt][c], d);
                }
            }
        if (gid == 0) {
            #pragma unroll
            for (int nt = 0; nt < 4; ++nt)
                #pragma unroll
                for (int c = 0; c < 2; ++c) {
                    int col = nq * 32 + nt * 8 + 2 * tig + c;
                    atomicAdd(&sh_sum[col], s[nt][c]);
                    atomicAdd(&sh_sq[col],  q[nt][c]);
                    atomicAdd(&sh_agg[col], ag[nt][c]);
                }
        }
        __syncthreads();
        if (tid < NH) {
            atomicAdd(&g_sum_e[tid], sh_sum[tid]);
            atomicAdd(&g_sq_e[tid],  sh_sq[tid]);
            atomicAdd(&g_agg[bi * NH + tid], sh_agg[tid]);
        }
    }
}

// ---------------------------------------------------------------------------
// x path stats: partial per-channel sums of x_new = Ux + agg
// ---------------------------------------------------------------------------
__global__ void __launch_bounds__(128) xstats_kernel()
{
    int h = threadIdx.x;
    float s = 0.f, q = 0.f;
    for (int r = blockIdx.x; r < NBV; r += gridDim.x) {
        float v = g_lin[r * NH + h] + g_agg[r * NH + h];
        s += v; q += v * v;
    }
    atomicAdd(&g_xsum[h], s);
    atomicAdd(&g_xsq[h],  q);
}

// ---------------------------------------------------------------------------
// x path apply: BN + ReLU
// ---------------------------------------------------------------------------
__global__ void __launch_bounds__(256) xapply_kernel(
    const float* __restrict__ gx, const float* __restrict__ bx,
    float* __restrict__ xout)
{
    __shared__ float sc[NH], sh[NH];
    int tid = threadIdx.x;
    if (tid < NH) {
        float m   = g_xsum[tid] * (1.f / NBV);
        float var = g_xsq[tid]  * (1.f / NBV) - m * m;
        float scl = gx[tid] * rsqrtf(var + BN_EPS);
        sc[tid] = scl; sh[tid] = bx[tid] - m * scl;
    }
    __syncthreads();
    int stride = gridDim.x * blockDim.x;
    for (int i = blockIdx.x * blockDim.x + tid; i < NBV * NH; i += stride) {
        int h = i & 127;
        float v = g_lin[i] + g_agg[i];
        xout[i] = fmaxf(v * sc[h] + sh[h], 0.f);
    }
}

// ---------------------------------------------------------------------------
extern "C" void kernel_launch(void* const* d_in, const int* in_sizes, int n_in,
                              void* d_out, int out_size)
{
    (void)in_sizes; (void)n_in; (void)out_size;
    const float* x  = (const float*)d_in[0];
    const float* e  = (const float*)d_in[1];
    // d_in[2] = graph (unused by reference)
    const float* Uw = (const float*)d_in[3];  const float* Ub = (const float*)d_in[4];
    const float* Vw = (const float*)d_in[5];  const float* Vb = (const float*)d_in[6];
    const float* Aw = (const float*)d_in[7];  const float* Ab = (const float*)d_in[8];
    const float* Bw = (const float*)d_in[9];  const float* Bb = (const float*)d_in[10];
    const float* Cw = (const float*)d_in[11]; const float* Cb = (const float*)d_in[12];
    const float* gx = (const float*)d_in[13]; const float* bx = (const float*)d_in[14];
    const float* ge = (const float*)d_in[15]; const float* be = (const float*)d_in[16];

    float* xout = (float*)d_out;               // (B,V,H)   = 102400 floats
    float* eout = xout + NBV * NH;             // (B,V,V,H) = 40,960,000 floats

    const int smem_bytes = (64 * CW + 128 * CW + 5 * NH) * 4;   // 54,784 B
    static int attr_done = 0;
    if (!attr_done) {
        cudaFuncSetAttribute(egemm_kernel<0>,
                             cudaFuncAttributeMaxDynamicSharedMemorySize, smem_bytes);
        cudaFuncSetAttribute(egemm_kernel<1>,
                             cudaFuncAttributeMaxDynamicSharedMemorySize, smem_bytes);
        attr_done = 1;
    }

    zero_kernel<<<(NBV * NH + 255) / 256, 256>>>(Cw);

    LinParams p;
    p.W0 = Uw; p.W1 = Vw; p.W2 = Aw; p.W3 = Bw;
    p.b0 = Ub; p.b1 = Vb; p.b2 = Ab; p.b3 = Bb;
    lin4_kernel<<<dim3(NBV / 80, 4), 256>>>(x, p);

    egemm_kernel<0><<<dim3((NV + BJ - 1) / BJ, NBV), 256, smem_bytes>>>(e, Cb, ge, be, eout);
    egemm_kernel<1><<<dim3((NV + BJ - 1) / BJ, NBV), 256, smem_bytes>>>(e, Cb, ge, be, eout);

    xstats_kernel<<<400, 128>>>();
    xapply_kernel<<<100, 256>>>(gx, bx, xout);
}

// round 15
// speedup vs baseline: 1.3118x; 1.0197x over previous
#include <cuda_runtime.h>
#include <math.h>
#include <stdint.h>

#define NB   2
#define NV   400
#define NH   128
#define NBV  800          // B*V
#define NBVV 320000       // B*V*V
#define BJ   64           // j rows per block in egemm
#define BN_EPS 1e-5f
#define CK   64           // k-chunk width
#define CW   68           // padded chunk row stride in u32 words (68 mod 32 = 4)

// ---- scratch (device globals; no allocation allowed) ----
__device__ __align__(16) float    g_lin[4 * NBV * NH];  // [0]=Ux [1]=Vx [2]=Ax [3]=Bx
__device__ __align__(16) float    g_agg[NBV * NH];      // sum_j Vx*gate
__device__ __align__(16) uint32_t g_cwt[NH * NH];       // tf32-converted Cw
__device__ float g_sum_e[NH];
__device__ float g_sq_e[NH];
__device__ float g_xsum[NH];
__device__ float g_xsq[NH];

struct LinParams {
    const float *W0, *W1, *W2, *W3;
    const float *b0, *b1, *b2, *b3;
};

__device__ __forceinline__ uint32_t f2tf32(float f) {
    uint32_t u;
    asm("cvt.rna.tf32.f32 %0, %1;" : "=r"(u) : "f"(f));
    return u;
}

#define MMA_TF32(d, a, b0v, b1v)                                             \
    asm volatile(                                                            \
        "mma.sync.aligned.m16n8k8.row.col.f32.tf32.tf32.f32 "                \
        "{%0,%1,%2,%3}, {%4,%5,%6,%7}, {%8,%9}, {%0,%1,%2,%3};"              \
        : "+f"((d)[0]), "+f"((d)[1]), "+f"((d)[2]), "+f"((d)[3])             \
        : "r"((a)[0]), "r"((a)[1]), "r"((a)[2]), "r"((a)[3]),                \
          "r"(b0v), "r"(b1v))

// ldmatrix x4: four 8x8 b16 tiles; for tf32, one 16B row-segment = 4 u32 words
#define LDSM_X4(r0, r1, r2, r3, addr)                                        \
    asm volatile(                                                            \
        "ldmatrix.sync.aligned.m8n8.x4.shared.b16 {%0,%1,%2,%3}, [%4];"      \
        : "=r"(r0), "=r"(r1), "=r"(r2), "=r"(r3) : "r"(addr))

// ---------------------------------------------------------------------------
// zero accumulators + pre-convert Cw to tf32
// ---------------------------------------------------------------------------
__global__ void zero_kernel(const float* __restrict__ Cw) {
    int i = blockIdx.x * blockDim.x + threadIdx.x;
    if (i < NBV * NH) g_agg[i] = 0.f;
    if (i < NH * NH)  g_cwt[i] = f2tf32(Cw[i]);
    if (i < NH) {
        g_sum_e[i] = 0.f; g_sq_e[i] = 0.f;
        g_xsum[i] = 0.f;  g_xsq[i] = 0.f;
    }
}

// ---------------------------------------------------------------------------
// four small linears: y = x @ W^T + b   (M=800, K=N=128, z selects matrix)
// ---------------------------------------------------------------------------
__global__ void __launch_bounds__(256) lin4_kernel(const float* __restrict__ x, LinParams p)
{
    __shared__ float As[80][33];
    __shared__ float Bs[32][NH + 4];
    int tid = threadIdx.x;
    int tx = tid & 15, ty = tid >> 4;
    int z = blockIdx.y;
    const float* W; const float* bias;
    if (z == 0)      { W = p.W0; bias = p.b0; }
    else if (z == 1) { W = p.W1; bias = p.b1; }
    else if (z == 2) { W = p.W2; bias = p.b2; }
    else             { W = p.W3; bias = p.b3; }
    int r0 = blockIdx.x * 80;
    const float* Arow = x + r0 * NH;

    float acc[5][8];
    #pragma unroll
    for (int s = 0; s < 5; ++s)
        #pragma unroll
        for (int c = 0; c < 8; ++c) acc[s][c] = 0.f;

    for (int kc = 0; kc < NH; kc += 32) {
        #pragma unroll
        for (int it = 0; it < 10; ++it) {
            int idx = tid + it * 256;
            int r = idx >> 5, k = idx & 31;
            As[r][k] = Arow[r * NH + kc + k];
        }
        #pragma unroll
        for (int it = 0; it < 16; ++it) {
            int idx = tid + it * 256;
            int n = idx >> 5, k = idx & 31;
            Bs[k][n] = W[n * NH + kc + k];
        }
        __syncthreads();
        #pragma unroll
        for (int k = 0; k < 32; ++k) {
            float a[5];
            #pragma unroll
            for (int s = 0; s < 5; ++s) a[s] = As[ty + 16 * s][k];
            float4 u = *(const float4*)&Bs[k][4 * tx];
            float4 w = *(const float4*)&Bs[k][64 + 4 * tx];
            #pragma unroll
            for (int s = 0; s < 5; ++s) {
                acc[s][0] += a[s] * u.x; acc[s][1] += a[s] * u.y;
                acc[s][2] += a[s] * u.z; acc[s][3] += a[s] * u.w;
                acc[s][4] += a[s] * w.x; acc[s][5] += a[s] * w.y;
                acc[s][6] += a[s] * w.z; acc[s][7] += a[s] * w.w;
            }
        }
        __syncthreads();
    }

    int n0 = 4 * tx, n1 = 64 + 4 * tx;
    float cb[8];
    *(float4*)&cb[0] = *(const float4*)&bias[n0];
    *(float4*)&cb[4] = *(const float4*)&bias[n1];
    float* out = g_lin + z * NBV * NH;
    #pragma unroll
    for (int s = 0; s < 5; ++s) {
        int r = r0 + ty + 16 * s;
        float ov[8];
        #pragma unroll
        for (int c = 0; c < 8; ++c) ov[c] = acc[s][c] + cb[c];
        *(float4*)&out[r * NH + n0] = *(float4*)&ov[0];
        *(float4*)&out[r * NH + n1] = *(float4*)&ov[4];
    }
}

// ---------------------------------------------------------------------------
// tf32 tensor-core fused kernel; fragment loads via ldmatrix (LDSM.x4):
//   APPLY=0 (stats): Ce GEMM -> e_new in regs -> per-channel sum/sumsq + agg
//   APPLY=1 (apply): Ce GEMM (recompute) -> BN apply + ReLU -> store eout
// grid: (7, 800), block 256 (8 warps); warp w: mq=w>>2, nq=w&3
// ---------------------------------------------------------------------------
template <int APPLY>
__global__ void __launch_bounds__(256, 3) egemm_kernel(
    const float* __restrict__ e, const float* __restrict__ Cb,
    const float* __restrict__ ge, const float* __restrict__ be,
    float* __restrict__ eout)
{
    extern __shared__ uint32_t dyn[];
    uint32_t* sE = dyn;                    // [64][CW] tf32 chunk
    uint32_t* sB = dyn + 64 * CW;          // [128][CW] tf32 chunk
    float* aux   = (float*)(dyn + 64 * CW + 128 * CW);
    float* sh_sum = aux;                   // [128] (apply: scE)
    float* sh_sq  = aux + NH;              // [128] (apply: shE)
    float* sh_agg = aux + 2 * NH;          // [128]
    float* cbS    = aux + 3 * NH;          // [128]
    float* bxS    = aux + 4 * NH;          // [128]

    int tid  = threadIdx.x;
    int lane = tid & 31;
    int wid  = tid >> 5;
    int gid  = lane >> 2, tig = lane & 3;
    int mq = wid >> 2;        // 0..1
    int nq = wid & 3;         // 0..3

    int bi = blockIdx.y;              // b*V + i
    int b  = bi / NV;
    int j0 = blockIdx.x * BJ;
    int rows = NV - j0; if (rows > BJ) rows = BJ;

    const float* Erow = e + ((size_t)bi * NV + j0) * NH;

    if (tid < NH) {
        cbS[tid] = Cb[tid];
        bxS[tid] = g_lin[3 * NBV * NH + bi * NH + tid];   // Bx row
        if (APPLY) {
            float m   = g_sum_e[tid] * (1.f / NBVV);
            float var = g_sq_e[tid]  * (1.f / NBVV) - m * m;
            float sc  = ge[tid] * rsqrtf(var + BN_EPS);
            sh_sum[tid] = sc;                       // scE
            sh_sq[tid]  = be[tid] - m * sc;         // shE
        } else {
            sh_sum[tid] = 0.f; sh_sq[tid] = 0.f; sh_agg[tid] = 0.f;
        }
    }

    // ---- ldmatrix lane addressing (bytes) ----
    // A x4 tiles: m0=(rows r..r+7, k0..k0+3) m1=(r+8.., k0..3) m2=(r.., k0+4..7) m3=(r+8.., k0+4..7)
    //   lanes 0-7 -> m0 rows, 8-15 -> m1, 16-23 -> m2, 24-31 -> m3
    // B x4 tiles (two n-octets): m0=(n..n+7,k0) m1=(n..n+7,k0+4) m2=(n+8..,k0) m3=(n+8..,k0+4)
    uint32_t eBase = (uint32_t)__cvta_generic_to_shared(sE);
    uint32_t bBase = (uint32_t)__cvta_generic_to_shared(sB);
    uint32_t lane7 = lane & 7;
    uint32_t s3 = (lane >> 3) & 1;
    uint32_t s4 = (lane >> 4) & 1;
    uint32_t aA0 = eBase + 4u * ((mq * 32 + 0 * 16 + s3 * 8 + lane7) * CW + s4 * 4);
    uint32_t aA1 = eBase + 4u * ((mq * 32 + 1 * 16 + s3 * 8 + lane7) * CW + s4 * 4);
    uint32_t bA0 = bBase + 4u * ((nq * 32 + 0 * 16 + s4 * 8 + lane7) * CW + s3 * 4);
    uint32_t bA1 = bBase + 4u * ((nq * 32 + 1 * 16 + s4 * 8 + lane7) * CW + s3 * 4);

    float acc[2][4][4];
    #pragma unroll
    for (int mt = 0; mt < 2; ++mt)
        #pragma unroll
        for (int nt = 0; nt < 4; ++nt)
            #pragma unroll
            for (int c = 0; c < 4; ++c) acc[mt][nt][c] = 0.f;

    // ---- k-chunked mainloop: 2 chunks of 64 ----
    #pragma unroll
    for (int kc = 0; kc < NH; kc += CK) {
        // stage E chunk (64 rows x 64 cols, cvt to tf32)
        #pragma unroll
        for (int it = 0; it < 4; ++it) {
            int idx = tid + it * 256;           // 0..1023
            int r = idx >> 4, c4 = (idx & 15) * 4;
            float4 v = make_float4(0.f, 0.f, 0.f, 0.f);
            if (r < rows) v = *(const float4*)&Erow[r * NH + kc + c4];
            uint32_t* d = &sE[r * CW + c4];
            d[0] = f2tf32(v.x); d[1] = f2tf32(v.y);
            d[2] = f2tf32(v.z); d[3] = f2tf32(v.w);
        }
        // stage Cw chunk (128 rows x 64 cols, pre-converted)
        #pragma unroll
        for (int it = 0; it < 8; ++it) {
            int idx = tid + it * 256;           // 0..2047
            int r = idx >> 4, c4 = (idx & 15) * 4;
            *(uint4*)&sB[r * CW + c4] = *(const uint4*)&g_cwt[r * NH + kc + c4];
        }
        __syncthreads();

        #pragma unroll
        for (int k0 = 0; k0 < CK; k0 += 8) {
            uint32_t off = 4u * k0;
            uint32_t A0[4], A1[4], B0[4], B1[4];
            LDSM_X4(A0[0], A0[1], A0[2], A0[3], aA0 + off);
            LDSM_X4(A1[0], A1[1], A1[2], A1[3], aA1 + off);
            LDSM_X4(B0[0], B0[1], B0[2], B0[3], bA0 + off);
            LDSM_X4(B1[0], B1[1], B1[2], B1[3], bA1 + off);
            MMA_TF32(acc[0][0], A0, B0[0], B0[1]);
            MMA_TF32(acc[1][0], A1, B0[0], B0[1]);
            MMA_TF32(acc[0][1], A0, B0[2], B0[3]);
            MMA_TF32(acc[1][1], A1, B0[2], B0[3]);
            MMA_TF32(acc[0][2], A0, B1[0], B1[1]);
            MMA_TF32(acc[1][2], A1, B1[0], B1[1]);
            MMA_TF32(acc[0][3], A0, B1[2], B1[3]);
            MMA_TF32(acc[1][3], A1, B1[2], B1[3]);
        }
        __syncthreads();
    }

    // ---- epilogue (Ax/Vx read directly from global; L1/L2 absorb reuse) ----
    const float* AxG = g_lin + 2 * NBV * NH;
    const float* VxG = g_lin + 1 * NBV * NH;

    if (APPLY) {
        #pragma unroll
        for (int mt = 0; mt < 2; ++mt) {
            #pragma unroll
            for (int half = 0; half < 2; ++half) {
                int rr = mq * 32 + mt * 16 + half * 8 + gid;
                if (rr < rows) {
                    size_t xrow = ((size_t)(b * NV + j0 + rr)) * NH;
                    size_t grow = ((size_t)bi * NV + j0 + rr) * NH;
                    #pragma unroll
                    for (int nt = 0; nt < 4; ++nt) {
                        int c0 = nq * 32 + nt * 8 + 2 * tig;
                        float2 axv = __ldg((const float2*)&AxG[xrow + c0]);
                        float ev0 = acc[mt][nt][half * 2]     + cbS[c0]     + axv.x + bxS[c0];
                        float ev1 = acc[mt][nt][half * 2 + 1] + cbS[c0 + 1] + axv.y + bxS[c0 + 1];
                        float2 st;
                        st.x = fmaxf(ev0 * sh_sum[c0]     + sh_sq[c0],     0.f);
                        st.y = fmaxf(ev1 * sh_sum[c0 + 1] + sh_sq[c0 + 1], 0.f);
                        *(float2*)&eout[grow + c0] = st;
                    }
                }
            }
        }
    } else {
        float s[4][2], q[4][2], ag[4][2];
        #pragma unroll
        for (int nt = 0; nt < 4; ++nt)
            #pragma unroll
            for (int c = 0; c < 2; ++c) { s[nt][c] = 0.f; q[nt][c] = 0.f; ag[nt][c] = 0.f; }

        #pragma unroll
        for (int mt = 0; mt < 2; ++mt) {
            #pragma unroll
            for (int half = 0; half < 2; ++half) {
                int rr = mq * 32 + mt * 16 + half * 8 + gid;
                if (rr < rows) {
                    size_t xrow = ((size_t)(b * NV + j0 + rr)) * NH;
                    #pragma unroll
                    for (int nt = 0; nt < 4; ++nt) {
                        int c0 = nq * 32 + nt * 8 + 2 * tig;
                        float2 axv = __ldg((const float2*)&AxG[xrow + c0]);
                        float2 vxv = __ldg((const float2*)&VxG[xrow + c0]);
                        float ev0 = acc[mt][nt][half * 2]     + cbS[c0]     + axv.x + bxS[c0];
                        float ev1 = acc[mt][nt][half * 2 + 1] + cbS[c0 + 1] + axv.y + bxS[c0 + 1];
                        float g0 = 1.f / (1.f + __expf(-ev0));
                        float g1 = 1.f / (1.f + __expf(-ev1));
                        s[nt][0] += ev0;       s[nt][1] += ev1;
                        q[nt][0] += ev0 * ev0; q[nt][1] += ev1 * ev1;
                        ag[nt][0] += vxv.x * g0;
                        ag[nt][1] += vxv.y * g1;
                    }
                }
            }
        }
        // reduce across gid lanes (xor 16/8/4 preserves tig)
        #pragma unroll
        for (int nt = 0; nt < 4; ++nt)
            #pragma unroll
            for (int c = 0; c < 2; ++c) {
                #pragma unroll
                for (int d = 16; d >= 4; d >>= 1) {
                    s[nt][c]  += __shfl_xor_sync(0xffffffffu, s[nt][c],  d);
                    q[nt][c]  += __shfl_xor_sync(0xffffffffu, q[nt][c],  d);
                    ag[nt][c] += __shfl_xor_sync(0xffffffffu, ag[nt][c], d);
                }
            }
        if (gid == 0) {
            #pragma unroll
            for (int nt = 0; nt < 4; ++nt)
                #pragma unroll
                for (int c = 0; c < 2; ++c) {
                    int col = nq * 32 + nt * 8 + 2 * tig + c;
                    atomicAdd(&sh_sum[col], s[nt][c]);
                    atomicAdd(&sh_sq[col],  q[nt][c]);
                    atomicAdd(&sh_agg[col], ag[nt][c]);
                }
        }
        __syncthreads();
        if (tid < NH) {
            atomicAdd(&g_sum_e[tid], sh_sum[tid]);
            atomicAdd(&g_sq_e[tid],  sh_sq[tid]);
            atomicAdd(&g_agg[bi * NH + tid], sh_agg[tid]);
        }
    }
}

// ---------------------------------------------------------------------------
// x path stats: partial per-channel sums of x_new = Ux + agg
// ---------------------------------------------------------------------------
__global__ void __launch_bounds__(128) xstats_kernel()
{
    int h = threadIdx.x;
    float s = 0.f, q = 0.f;
    for (int r = blockIdx.x; r < NBV; r += gridDim.x) {
        float v = g_lin[r * NH + h] + g_agg[r * NH + h];
        s += v; q += v * v;
    }
    atomicAdd(&g_xsum[h], s);
    atomicAdd(&g_xsq[h],  q);
}

// ---------------------------------------------------------------------------
// x path apply: BN + ReLU
// ---------------------------------------------------------------------------
__global__ void __launch_bounds__(256) xapply_kernel(
    const float* __restrict__ gx, const float* __restrict__ bx,
    float* __restrict__ xout)
{
    __shared__ float sc[NH], sh[NH];
    int tid = threadIdx.x;
    if (tid < NH) {
        float m   = g_xsum[tid] * (1.f / NBV);
        float var = g_xsq[tid]  * (1.f / NBV) - m * m;
        float scl = gx[tid] * rsqrtf(var + BN_EPS);
        sc[tid] = scl; sh[tid] = bx[tid] - m * scl;
    }
    __syncthreads();
    int stride = gridDim.x * blockDim.x;
    for (int i = blockIdx.x * blockDim.x + tid; i < NBV * NH; i += stride) {
        int h = i & 127;
        float v = g_lin[i] + g_agg[i];
        xout[i] = fmaxf(v * sc[h] + sh[h], 0.f);
    }
}

// ---------------------------------------------------------------------------
extern "C" void kernel_launch(void* const* d_in, const int* in_sizes, int n_in,
                              void* d_out, int out_size)
{
    (void)in_sizes; (void)n_in; (void)out_size;
    const float* x  = (const float*)d_in[0];
    const float* e  = (const float*)d_in[1];
    // d_in[2] = graph (unused by reference)
    const float* Uw = (const float*)d_in[3];  const float* Ub = (const float*)d_in[4];
    const float* Vw = (const float*)d_in[5];  const float* Vb = (const float*)d_in[6];
    const float* Aw = (const float*)d_in[7];  const float* Ab = (const float*)d_in[8];
    const float* Bw = (const float*)d_in[9];  const float* Bb = (const float*)d_in[10];
    const float* Cw = (const float*)d_in[11]; const float* Cb = (const float*)d_in[12];
    const float* gx = (const float*)d_in[13]; const float* bx = (const float*)d_in[14];
    const float* ge = (const float*)d_in[15]; const float* be = (const float*)d_in[16];

    float* xout = (float*)d_out;               // (B,V,H)   = 102400 floats
    float* eout = xout + NBV * NH;             // (B,V,V,H) = 40,960,000 floats

    const int smem_bytes = (64 * CW + 128 * CW + 5 * NH) * 4;   // 54,784 B
    static int attr_done = 0;
    if (!attr_done) {
        cudaFuncSetAttribute(egemm_kernel<0>,
                             cudaFuncAttributeMaxDynamicSharedMemorySize, smem_bytes);
        cudaFuncSetAttribute(egemm_kernel<1>,
                             cudaFuncAttributeMaxDynamicSharedMemorySize, smem_bytes);
        attr_done = 1;
    }

    zero_kernel<<<(NBV * NH + 255) / 256, 256>>>(Cw);

    LinParams p;
    p.W0 = Uw; p.W1 = Vw; p.W2 = Aw; p.W3 = Bw;
    p.b0 = Ub; p.b1 = Vb; p.b2 = Ab; p.b3 = Bb;
    lin4_kernel<<<dim3(NBV / 80, 4), 256>>>(x, p);

    egemm_kernel<0><<<dim3((NV + BJ - 1) / BJ, NBV), 256, smem_bytes>>>(e, Cb, ge, be, eout);
    egemm_kernel<1><<<dim3((NV + BJ - 1) / BJ, NBV), 256, smem_bytes>>>(e, Cb, ge, be, eout);

    xstats_kernel<<<400, 128>>>();
    xapply_kernel<<<100, 256>>>(gx, bx, xout);
}